// round 7
// baseline (speedup 1.0000x reference)
#include <cuda_runtime.h>
#include <cuda_bf16.h>
#include <cstdint>

#define BATCH 4
#define EMB   256
#define NTOK  4096
#define NITER_TC (NTOK / 64)
#define LOG2E 1.4426950408889634f

// Scratch: q,k as [b][n][d] tf32-rounded fp32 (q pre-scaled by log2e/16);
// g_v [b][n][d] fp32 (SIMT fallback); g_vt [b][d][n] bf16 (tcgen05 path).
__device__ float g_q [(size_t)BATCH * NTOK * EMB];
__device__ float g_k [(size_t)BATCH * NTOK * EMB];
__device__ float g_v [(size_t)BATCH * NTOK * EMB];
__device__ __nv_bfloat16 g_vt[(size_t)BATCH * EMB * NTOK];

// ---------------------------------------------------------------------------
// Arch-specific feature gate: tcgen05 exists only in 'a'-suffix device passes.
// ---------------------------------------------------------------------------
#if defined(__CUDA_ARCH_FEAT_SM103_ALL) || defined(__CUDA_ARCH_FEAT_SM100_ALL) || \
    defined(__CUDA_ARCH_FEAT_SM101_ALL) || defined(__CUDA_ARCH_SPECIFIC__)
#define TC_OK 1
#else
#define TC_OK 0
#endif

__device__ __forceinline__ float f2tf32(float f) {
    uint32_t u;
    asm("cvt.rna.tf32.f32 %0, %1;" : "=r"(u) : "f"(f));
    return __uint_as_float(u);
}

// ============================================================================
// QKV projection (SIMT fp32). 64x64 tiles, 256 threads, 4x4 micro-tile.
// q scaled by log2e/16 (folds 1/sqrt(C) and the exp->exp2 conversion).
// ============================================================================
__global__ __launch_bounds__(256) void qkv_proj_kernel(
    const float* __restrict__ x,
    const float* __restrict__ Wq, const float* __restrict__ bq,
    const float* __restrict__ Wk, const float* __restrict__ bk,
    const float* __restrict__ Wv, const float* __restrict__ bv)
{
    __shared__ float Xs[64 * 32];
    __shared__ float Ws[64 * 32];

    const int n0 = blockIdx.x * 64;
    const int d0 = blockIdx.y * 64;
    const int z  = blockIdx.z;
    const int b  = z / 3;
    const int which = z - 3 * b;

    const float* W; const float* bias; float scl;
    if (which == 0)      { W = Wq; bias = bq; scl = 0.0625f * LOG2E; }
    else if (which == 1) { W = Wk; bias = bk; scl = 1.0f; }
    else                 { W = Wv; bias = bv; scl = 1.0f; }

    const int tid = threadIdx.x;
    const int tx = tid & 15;
    const int ty = tid >> 4;

    float acc[4][4];
    #pragma unroll
    for (int i = 0; i < 4; ++i)
        #pragma unroll
        for (int j = 0; j < 4; ++j) acc[i][j] = 0.f;

    const float* xb = x + (size_t)b * EMB * NTOK + n0;

    for (int c0 = 0; c0 < EMB; c0 += 32) {
        {
            const int nl = tid & 63;
            const int cg = tid >> 6;
            const int sw = (nl >> 2) & 7;
            #pragma unroll
            for (int it = 0; it < 8; ++it) {
                const int cc = cg * 8 + it;
                const int pc = (((cc >> 2) ^ sw) << 2) | (cc & 3);
                Xs[nl * 32 + pc] = xb[(size_t)(c0 + cc) * NTOK + nl];
            }
        }
        {
            const int cl = tid & 31;
            const int dg = tid >> 5;
            #pragma unroll
            for (int it = 0; it < 8; ++it) {
                const int dd = dg * 8 + it;
                const int sw = (dd >> 2) & 7;
                const int pc = (((cl >> 2) ^ sw) << 2) | (cl & 3);
                Ws[dd * 32 + pc] = W[(size_t)(d0 + dd) * EMB + c0 + cl];
            }
        }
        __syncthreads();

        #pragma unroll
        for (int c = 0; c < 32; c += 4) {
            const int c4 = c >> 2;
            float4 xv[4], wv[4];
            #pragma unroll
            for (int i = 0; i < 4; ++i) {
                const int r = ty * 4 + i;
                xv[i] = *(const float4*)&Xs[r * 32 + ((c4 ^ ((r >> 2) & 7)) << 2)];
            }
            #pragma unroll
            for (int j = 0; j < 4; ++j) {
                const int r = tx * 4 + j;
                wv[j] = *(const float4*)&Ws[r * 32 + ((c4 ^ ((r >> 2) & 7)) << 2)];
            }
            #pragma unroll
            for (int i = 0; i < 4; ++i)
                #pragma unroll
                for (int j = 0; j < 4; ++j)
                    acc[i][j] += xv[i].x * wv[j].x + xv[i].y * wv[j].y
                               + xv[i].z * wv[j].z + xv[i].w * wv[j].w;
        }
        __syncthreads();
    }

    if (which == 2) {
        float* ob = g_v + ((size_t)b * NTOK + n0) * EMB + d0;
        #pragma unroll
        for (int i = 0; i < 4; ++i) {
            const int r = ty * 4 + i;
            float4 o;
            o.x = acc[i][0] + bias[d0 + tx * 4 + 0];
            o.y = acc[i][1] + bias[d0 + tx * 4 + 1];
            o.z = acc[i][2] + bias[d0 + tx * 4 + 2];
            o.w = acc[i][3] + bias[d0 + tx * 4 + 3];
            *(float4*)&ob[r * EMB + tx * 4] = o;
        }
        __nv_bfloat16* vb = g_vt + (size_t)b * EMB * NTOK + n0 + ty * 4;
        #pragma unroll
        for (int j = 0; j < 4; ++j) {
            const int d = d0 + tx * 4 + j;
            const float bj = bias[d];
            uint32_t lo, hi;
            asm("cvt.rn.bf16x2.f32 %0, %1, %2;" : "=r"(lo)
                : "f"(acc[1][j] + bj), "f"(acc[0][j] + bj));
            asm("cvt.rn.bf16x2.f32 %0, %1, %2;" : "=r"(hi)
                : "f"(acc[3][j] + bj), "f"(acc[2][j] + bj));
            uint2 o; o.x = lo; o.y = hi;
            *(uint2*)&vb[(size_t)d * NTOK] = o;
        }
    } else {
        float* out = (which == 0) ? g_q : g_k;
        float* ob = out + ((size_t)b * NTOK + n0) * EMB + d0;
        #pragma unroll
        for (int i = 0; i < 4; ++i) {
            const int r = ty * 4 + i;
            float4 o;
            o.x = f2tf32((acc[i][0] + bias[d0 + tx * 4 + 0]) * scl);
            o.y = f2tf32((acc[i][1] + bias[d0 + tx * 4 + 1]) * scl);
            o.z = f2tf32((acc[i][2] + bias[d0 + tx * 4 + 2]) * scl);
            o.w = f2tf32((acc[i][3] + bias[d0 + tx * 4 + 3]) * scl);
            *(float4*)&ob[r * EMB + tx * 4] = o;
        }
    }
}

// ============================================================================
// SIMT fallback flash attention (uses exp2f; q pre-scaled by log2e/16).
// ============================================================================
#define SQBLK 64
#define SKBLK 64
#define PSTR  68
#define ATT_SMEM_FLOATS (3 * SQBLK * EMB + SQBLK * PSTR + 3 * SQBLK)
#define ATT_SMEM_BYTES  (ATT_SMEM_FLOATS * 4)

__global__ __launch_bounds__(256, 1) void attn_simt_kernel(float* __restrict__ out)
{
    extern __shared__ float smf[];
    float* Qs  = smf;
    float* Ks  = Qs + SQBLK * EMB;
    float* Vs  = Ks + SQBLK * EMB;
    float* Ps  = Vs + SQBLK * EMB;
    float* m_s = Ps + SQBLK * PSTR;
    float* l_s = m_s + SQBLK;
    float* a_s = l_s + SQBLK;

    const int q0  = blockIdx.x * SQBLK;
    const int b   = blockIdx.y;
    const int tid = threadIdx.x;
    const int tx  = tid & 15;
    const int ty  = tid >> 4;

    const float* gq = g_q + (size_t)b * NTOK * EMB;
    const float* gk = g_k + (size_t)b * NTOK * EMB;
    const float* gv = g_v + (size_t)b * NTOK * EMB;

    #pragma unroll
    for (int it = 0; it < SQBLK * EMB / 4 / 256; ++it) {
        const int idx = tid + it * 256;
        const int r  = idx >> 6;
        const int c4 = idx & 63;
        *(float4*)&Qs[r * EMB + c4 * 4] =
            *(const float4*)&gq[(size_t)(q0 + r) * EMB + c4 * 4];
    }
    if (tid < SQBLK) { m_s[tid] = -1e30f; l_s[tid] = 0.f; }

    float o[4][16];
    #pragma unroll
    for (int i = 0; i < 4; ++i)
        #pragma unroll
        for (int u = 0; u < 16; ++u) o[i][u] = 0.f;

    __syncthreads();

    for (int k0 = 0; k0 < NTOK; k0 += SKBLK) {
        #pragma unroll
        for (int it = 0; it < SKBLK * EMB / 4 / 256; ++it) {
            const int idx = tid + it * 256;
            const int r   = idx >> 6;
            const int c4  = idx & 63;
            const int pc4 = c4 ^ ((r >> 2) & 7);
            *(float4*)&Ks[r * EMB + pc4 * 4] =
                *(const float4*)&gk[(size_t)(k0 + r) * EMB + c4 * 4];
            *(float4*)&Vs[r * EMB + c4 * 4] =
                *(const float4*)&gv[(size_t)(k0 + r) * EMB + c4 * 4];
        }
        __syncthreads();

        float acc[4][4];
        #pragma unroll
        for (int i = 0; i < 4; ++i)
            #pragma unroll
            for (int j = 0; j < 4; ++j) acc[i][j] = 0.f;

        const int ksw = tx & 7;
        #pragma unroll 2
        for (int c = 0; c < EMB; c += 4) {
            const int c4 = c >> 2;
            float4 qv[4], kv[4];
            #pragma unroll
            for (int i = 0; i < 4; ++i)
                qv[i] = *(const float4*)&Qs[(ty * 4 + i) * EMB + c];
            #pragma unroll
            for (int j = 0; j < 4; ++j)
                kv[j] = *(const float4*)&Ks[(tx * 4 + j) * EMB + ((c4 ^ ksw) << 2)];
            #pragma unroll
            for (int i = 0; i < 4; ++i)
                #pragma unroll
                for (int j = 0; j < 4; ++j)
                    acc[i][j] += qv[i].x * kv[j].x + qv[i].y * kv[j].y
                               + qv[i].z * kv[j].z + qv[i].w * kv[j].w;
        }

        #pragma unroll
        for (int i = 0; i < 4; ++i) {
            const int r = ty * 4 + i;
            float rmax = fmaxf(fmaxf(acc[i][0], acc[i][1]),
                               fmaxf(acc[i][2], acc[i][3]));
            #pragma unroll
            for (int off = 1; off < 16; off <<= 1)
                rmax = fmaxf(rmax, __shfl_xor_sync(0xffffffffu, rmax, off));
            const float mo = m_s[r];
            const float mn = fmaxf(mo, rmax);
            float4 p;
            p.x = exp2f(acc[i][0] - mn);
            p.y = exp2f(acc[i][1] - mn);
            p.z = exp2f(acc[i][2] - mn);
            p.w = exp2f(acc[i][3] - mn);
            *(float4*)&Ps[r * PSTR + tx * 4] = p;
            float rsum = p.x + p.y + p.z + p.w;
            #pragma unroll
            for (int off = 1; off < 16; off <<= 1)
                rsum += __shfl_xor_sync(0xffffffffu, rsum, off);
            if (tx == 0) {
                const float a = exp2f(mo - mn);
                m_s[r] = mn;
                l_s[r] = l_s[r] * a + rsum;
                a_s[r] = a;
            }
        }
        __syncthreads();

        {
            float al[4];
            #pragma unroll
            for (int i = 0; i < 4; ++i) al[i] = a_s[tx + 16 * i];
            #pragma unroll
            for (int i = 0; i < 4; ++i)
                #pragma unroll
                for (int u = 0; u < 16; ++u) o[i][u] *= al[i];

            #pragma unroll 2
            for (int k = 0; k < SKBLK; ++k) {
                float p[4];
                #pragma unroll
                for (int i = 0; i < 4; ++i)
                    p[i] = Ps[(tx + 16 * i) * PSTR + k];
                const float* vrow = &Vs[k * EMB + ty * 16];
                const float4 v0 = *(const float4*)&vrow[0];
                const float4 v1 = *(const float4*)&vrow[4];
                const float4 v2 = *(const float4*)&vrow[8];
                const float4 v3 = *(const float4*)&vrow[12];
                #pragma unroll
                for (int i = 0; i < 4; ++i) {
                    o[i][0]  += p[i] * v0.x;  o[i][1]  += p[i] * v0.y;
                    o[i][2]  += p[i] * v0.z;  o[i][3]  += p[i] * v0.w;
                    o[i][4]  += p[i] * v1.x;  o[i][5]  += p[i] * v1.y;
                    o[i][6]  += p[i] * v1.z;  o[i][7]  += p[i] * v1.w;
                    o[i][8]  += p[i] * v2.x;  o[i][9]  += p[i] * v2.y;
                    o[i][10] += p[i] * v2.z;  o[i][11] += p[i] * v2.w;
                    o[i][12] += p[i] * v3.x;  o[i][13] += p[i] * v3.y;
                    o[i][14] += p[i] * v3.z;  o[i][15] += p[i] * v3.w;
                }
            }
        }
        __syncthreads();
    }

    float* ob = out + ((size_t)b * NTOK + q0) * EMB + ty * 16;
    #pragma unroll
    for (int i = 0; i < 4; ++i) {
        const float linv = 1.f / l_s[tx + 16 * i];
        float* dst = &ob[(size_t)(tx + 16 * i) * EMB];
        #pragma unroll
        for (int u = 0; u < 16; u += 4) {
            float4 r;
            r.x = o[i][u + 0] * linv;
            r.y = o[i][u + 1] * linv;
            r.z = o[i][u + 2] * linv;
            r.w = o[i][u + 3] * linv;
            *(float4*)&dst[u] = r;
        }
    }
}

// ============================================================================
// tcgen05 pipelined attention v2. One CTA = (128-query tile, batch),
// 256 threads (2 warpgroups: wg0 -> S cols 0-31, wg1 -> S cols 32-63).
// SMEM: Q[128x256] tf32 (128KB) + K[64x256] tf32 (64KB) + Vt[256x64] bf16 (32KB).
// TMEM: S0@0(64), S1@64(64), P(bf16x2)@128(32), O@256(256).
// Schedule/iter: wait MMA1(n) -> load K(n+1) -> issue MMA1(n+1)
//                -> softmax(n) (overlaps MMA1(n+1)) -> wait MMA2(n-1)
//                -> load V(n) + STTM P(n) -> issue MMA2(n).
// ============================================================================
#define TCQ 128
#define TCK 64
#define SM_Q    0
#define SM_K    131072
#define SM_V    196608
#define SM_PTR  229376
#define SM_M1   229384
#define SM_M2   229392
#define SM_L    229408
#define ATT_TC_SMEM (229408 + 2 * 128 * 4)
#define TM_S 0
#define TM_P 128
#define TM_O 256

#if TC_OK
__device__ __forceinline__ uint32_t smem_u32(const void* p) {
    uint32_t a;
    asm("{ .reg .u64 t; cvta.to.shared.u64 t, %1; cvt.u32.u64 %0, t; }"
        : "=r"(a) : "l"(p));
    return a;
}
__device__ __forceinline__ uint32_t elect_one() {
    uint32_t pred;
    asm volatile("{\n\t.reg .pred p;\n\telect.sync _|p, 0xFFFFFFFF;\n\t"
                 "selp.b32 %0, 1, 0, p;\n\t}" : "=r"(pred));
    return pred;
}

#define MBAR_INIT(mbar, cnt) \
    asm volatile("mbarrier.init.shared.b64 [%0], %1;" :: "r"(mbar), "r"(cnt) : "memory")
#define MBAR_INVAL(mbar) \
    asm volatile("mbarrier.inval.shared.b64 [%0];" :: "r"(mbar) : "memory")
#define MBAR_WAIT(mbar, parity) do {                                             \
    uint32_t _mb = (mbar); uint32_t _ph = (parity); uint32_t _done;              \
    asm volatile("{\n\t.reg .pred p;\n\t"                                        \
        "mbarrier.try_wait.parity.acquire.cta.shared::cta.b64 p, [%1], %2;\n\t"  \
        "selp.b32 %0, 1, 0, p;\n\t}"                                             \
        : "=r"(_done) : "r"(_mb), "r"(_ph) : "memory");                          \
    if (!_done) {                                                                \
        asm volatile("{\n\t.reg .pred P1;\n\t"                                   \
            "WL_%=:\n\t"                                                         \
            "mbarrier.try_wait.parity.acquire.cta.shared::cta.b64 P1, [%0], %1, 0x989680;\n\t" \
            "@P1 bra.uni WD_%=;\n\t"                                             \
            "bra.uni WL_%=;\n\t"                                                 \
            "WD_%=:\n\t}" :: "r"(_mb), "r"(_ph) : "memory");                     \
    }                                                                            \
} while (0)

#define TC_ALLOC(dst_smem, ncols) \
    asm volatile("tcgen05.alloc.cta_group::1.sync.aligned.shared::cta.b32 [%0], %1;" \
                 :: "r"(dst_smem), "r"(ncols) : "memory")
#define TC_RELINQ() \
    asm volatile("tcgen05.relinquish_alloc_permit.cta_group::1.sync.aligned;")
#define TC_DEALLOC(tmem, ncols) \
    asm volatile("tcgen05.dealloc.cta_group::1.sync.aligned.b32 %0, %1;" \
                 :: "r"(tmem), "r"(ncols))
#define TC_COMMIT(mbar) \
    asm volatile("tcgen05.commit.cta_group::1.mbarrier::arrive::one.shared::cluster.b64 [%0];" \
                 :: "r"(mbar) : "memory")
#define TC_WAIT_LD()  asm volatile("tcgen05.wait::ld.sync.aligned;"  ::: "memory")
#define TC_WAIT_ST()  asm volatile("tcgen05.wait::st.sync.aligned;"  ::: "memory")
#define TC_FENCE_BEFORE() asm volatile("tcgen05.fence::before_thread_sync;" ::: "memory")
#define TC_FENCE_AFTER()  asm volatile("tcgen05.fence::after_thread_sync;"  ::: "memory")
#define FENCE_ASYNC_SHARED() asm volatile("fence.proxy.async.shared::cta;" ::: "memory")

#define LDTM_X32(r, addr) \
    asm volatile("tcgen05.ld.sync.aligned.32x32b.x32.b32 " \
        "{%0, %1, %2, %3, %4, %5, %6, %7, %8, %9, %10, %11, %12, %13, %14, %15, " \
        " %16, %17, %18, %19, %20, %21, %22, %23, %24, %25, %26, %27, %28, %29, %30, %31}, [%32];" \
        : "=r"((r)[0]),  "=r"((r)[1]),  "=r"((r)[2]),  "=r"((r)[3]),  \
          "=r"((r)[4]),  "=r"((r)[5]),  "=r"((r)[6]),  "=r"((r)[7]),  \
          "=r"((r)[8]),  "=r"((r)[9]),  "=r"((r)[10]), "=r"((r)[11]), \
          "=r"((r)[12]), "=r"((r)[13]), "=r"((r)[14]), "=r"((r)[15]), \
          "=r"((r)[16]), "=r"((r)[17]), "=r"((r)[18]), "=r"((r)[19]), \
          "=r"((r)[20]), "=r"((r)[21]), "=r"((r)[22]), "=r"((r)[23]), \
          "=r"((r)[24]), "=r"((r)[25]), "=r"((r)[26]), "=r"((r)[27]), \
          "=r"((r)[28]), "=r"((r)[29]), "=r"((r)[30]), "=r"((r)[31]) \
        : "r"(addr))

#define STTM_X16(addr, r) \
    asm volatile("tcgen05.st.sync.aligned.32x32b.x16.b32 [%0], " \
        "{%1, %2, %3, %4, %5, %6, %7, %8, %9, %10, %11, %12, %13, %14, %15, %16};" \
        :: "r"(addr), \
           "r"((r)[0]),  "r"((r)[1]),  "r"((r)[2]),  "r"((r)[3]),  \
           "r"((r)[4]),  "r"((r)[5]),  "r"((r)[6]),  "r"((r)[7]),  \
           "r"((r)[8]),  "r"((r)[9]),  "r"((r)[10]), "r"((r)[11]), \
           "r"((r)[12]), "r"((r)[13]), "r"((r)[14]), "r"((r)[15]) \
        : "memory")

__device__ __forceinline__ uint64_t make_desc(uint32_t smem_addr) {
    // SW128 K-major, version=1 (Blackwell), SBO=64, LBO=1
    return 0x4000404000010000ULL | ((uint64_t)(smem_addr >> 4) & 0x3FFF);
}
// tf32 idesc: dtype F32 (bit4), a/btype TF32=2 (bits7,10), N/8 @17, M/16 @24
#define IDESC1 ((1u << 4) | (2u << 7) | (2u << 10) | ((TCK / 8) << 17) | ((TCQ / 16) << 24))
// bf16 idesc: dtype F32, a/btype BF16=1, N=256, M=128
#define IDESC2 ((1u << 4) | (1u << 7) | (1u << 10) | ((EMB / 8) << 17) | ((TCQ / 16) << 24))

__device__ __forceinline__ void mma_tf32_ss(uint32_t d, uint64_t a, uint64_t b,
                                            uint32_t idesc, uint32_t en) {
    asm volatile("{\n\t.reg .pred p;\n\tsetp.ne.u32 p, %5, 0;\n\t"
        "tcgen05.mma.cta_group::1.kind::tf32 [%0], %1, %2, %3, {%4, %4, %4, %4}, p;\n\t}"
        :: "r"(d), "l"(a), "l"(b), "r"(idesc), "r"(0u), "r"(en) : "memory");
}
__device__ __forceinline__ void mma_f16_ts(uint32_t d, uint32_t a, uint64_t b,
                                           uint32_t idesc, uint32_t en) {
    asm volatile("{\n\t.reg .pred p;\n\tsetp.ne.u32 p, %5, 0;\n\t"
        "tcgen05.mma.cta_group::1.kind::f16 [%0], [%1], %2, %3, {%4, %4, %4, %4}, p;\n\t}"
        :: "r"(d), "r"(a), "l"(b), "r"(idesc), "r"(0u), "r"(en) : "memory");
}
__device__ __forceinline__ uint32_t sw128(uint32_t b) { return b ^ ((b >> 3) & 0x70); }

__device__ __forceinline__ void load_k_tile(char* sm, const float* gk, int tid) {
    #pragma unroll 8
    for (int it = 0; it < 16; ++it) {
        const int idx = tid + it * 256;
        const int r  = idx >> 6;
        const int c4 = idx & 63;
        float4 v = *(const float4*)&gk[(size_t)r * EMB + c4 * 4];
        uint32_t byte = (uint32_t)(((r >> 3) + (c4 >> 3) * 8) * 1024
                                   + (r & 7) * 128 + (c4 & 7) * 16);
        *(float4*)(sm + SM_K + sw128(byte)) = v;
    }
}
__device__ __forceinline__ void issue_mma1(uint32_t sdst, uint64_t qdesc,
                                           uint64_t kdesc, uint32_t mbar) {
    #pragma unroll
    for (int s = 0; s < 32; ++s) {
        const uint64_t qd = qdesc + (uint64_t)((s >> 2) * 1024 + (s & 3) * 2);
        const uint64_t kd = kdesc + (uint64_t)((s >> 2) * 512  + (s & 3) * 2);
        mma_tf32_ss(sdst, qd, kd, IDESC1, (uint32_t)(s > 0));
    }
    TC_COMMIT(mbar);
}
#endif  // TC_OK

__global__ __launch_bounds__(256, 1) void attn_tc_kernel(float* __restrict__ out)
{
#if TC_OK
    extern __shared__ char sm[];
    const uint32_t smb = smem_u32(sm);
    const int tid = threadIdx.x;
    const int wid = tid >> 5;
    const int sp  = wid & 3;          // subpartition (lane rows sp*32..sp*32+31)
    const int wg  = wid >> 2;         // warpgroup: S-column half
    const int lid = tid & 31;
    const int q0  = blockIdx.x * TCQ;
    const int b   = blockIdx.y;

    if (wid == 0) {
        TC_ALLOC(smb + SM_PTR, 512);
        TC_RELINQ();
        if (elect_one()) { MBAR_INIT(smb + SM_M1, 1); MBAR_INIT(smb + SM_M2, 1); }
    }
    __syncthreads();
    uint32_t tmem;
    asm volatile("ld.shared.b32 %0, [%1];" : "=r"(tmem) : "r"(smb + SM_PTR));
    const uint32_t woff = (uint32_t)sp << 21;

    const uint64_t qdesc = make_desc(smb + SM_Q);
    const uint64_t kdesc = make_desc(smb + SM_K);
    const uint64_t vdesc = make_desc(smb + SM_V);

    // ---- prologue: load Q (16x8 SW128 atoms) + K(0); issue MMA1(0) ----
    {
        const float* gq = g_q + ((size_t)b * NTOK + q0) * EMB;
        #pragma unroll 8
        for (int it = 0; it < 32; ++it) {
            const int idx = tid + it * 256;
            const int r  = idx >> 6;
            const int c4 = idx & 63;
            float4 v = *(const float4*)&gq[(size_t)r * EMB + c4 * 4];
            uint32_t byte = (uint32_t)(((r >> 3) + (c4 >> 3) * 16) * 1024
                                       + (r & 7) * 128 + (c4 & 7) * 16);
            *(float4*)(sm + SM_Q + sw128(byte)) = v;
        }
        load_k_tile(sm, g_k + (size_t)b * NTOK * EMB, tid);
    }
    FENCE_ASYNC_SHARED();
    __syncthreads();
    if (wid == 0) {
        TC_FENCE_AFTER();
        if (elect_one()) issue_mma1(tmem + TM_S, qdesc, kdesc, smb + SM_M1);
    }

    float lsum = 0.f;
    int ph1 = 0, ph2 = 0;

    for (int itn = 0; itn < NITER_TC; ++itn) {
        const int k0 = itn * TCK;

        // (a) wait MMA1(n): S(n) ready, K buffer free
        MBAR_WAIT(smb + SM_M1, ph1); ph1 ^= 1;
        TC_FENCE_AFTER();

        // (b) load K(n+1); issue MMA1(n+1) (runs concurrently with softmax below)
        if (itn < NITER_TC - 1) {
            load_k_tile(sm, g_k + ((size_t)b * NTOK + k0 + TCK) * EMB, tid);
            FENCE_ASYNC_SHARED();
            __syncthreads();
            if (wid == 0) {
                TC_FENCE_AFTER();
                if (elect_one())
                    issue_mma1(tmem + TM_S + (uint32_t)(((itn + 1) & 1) << 6),
                               qdesc, kdesc, smb + SM_M1);
            }
        }

        // (c) softmax on this wg's 32 columns: p = exp2(s); pack to bf16x2
        uint32_t pr[16];
        {
            const uint32_t sbase = tmem + TM_S + (uint32_t)((itn & 1) << 6)
                                 + (uint32_t)(wg << 5) + woff;
            uint32_t sreg[32];
            LDTM_X32(sreg, sbase);
            TC_WAIT_LD();
            float part = 0.f;
            #pragma unroll
            for (int j = 0; j < 16; ++j) {
                const float p0 = exp2f(__uint_as_float(sreg[2 * j]));
                const float p1 = exp2f(__uint_as_float(sreg[2 * j + 1]));
                part += p0 + p1;
                asm("cvt.rn.bf16x2.f32 %0, %1, %2;" : "=r"(pr[j]) : "f"(p1), "f"(p0));
            }
            lsum += part;
        }

        // (d) wait MMA2(n-1): P region + V buffer free
        if (itn > 0) { MBAR_WAIT(smb + SM_M2, ph2); ph2 ^= 1; }
        TC_FENCE_AFTER();

        // (e) load V(n) + store P(n); issue MMA2(n)
        {
            const __nv_bfloat16* gvt = g_vt + (size_t)b * EMB * NTOK + k0;
            #pragma unroll 8
            for (int it = 0; it < 8; ++it) {
                const int idx = tid + it * 256;
                const int r = idx >> 3;
                const int c = idx & 7;
                uint4 v = *(const uint4*)&gvt[(size_t)r * NTOK + c * 8];
                uint32_t byte = (uint32_t)((r >> 3) * 1024 + (r & 7) * 128 + c * 16);
                *(uint4*)(sm + SM_V + sw128(byte)) = v;
            }
            STTM_X16(tmem + TM_P + (uint32_t)(wg << 4) + woff, pr);
            TC_WAIT_ST();
        }
        TC_FENCE_BEFORE();
        FENCE_ASYNC_SHARED();
        __syncthreads();
        if (wid == 0) {
            TC_FENCE_AFTER();
            if (elect_one()) {
                #pragma unroll
                for (int s = 0; s < 4; ++s) {
                    mma_f16_ts(tmem + TM_O, tmem + TM_P + s * 8,
                               vdesc + (uint64_t)(s * 2), IDESC2,
                               (uint32_t)((itn > 0) | (s > 0)));
                }
                TC_COMMIT(smb + SM_M2);
            }
        }
    }

    // ---- epilogue: wait MMA2(last); combine l across warpgroups; write out ----
    MBAR_WAIT(smb + SM_M2, ph2); ph2 ^= 1;
    TC_FENCE_AFTER();
    {
        float* lpart = (float*)(sm + SM_L);
        const int row = sp * 32 + lid;
        lpart[wg * 128 + row] = lsum;
        __syncthreads();
        const float inv = 1.f / (lpart[row] + lpart[128 + row]);

        float* ob = out + ((size_t)b * NTOK + q0 + row) * EMB + wg * 128;
        #pragma unroll
        for (int ch = 0; ch < 4; ++ch) {
            uint32_t r[32];
            LDTM_X32(r, tmem + TM_O + (uint32_t)(wg * 128 + ch * 32) + woff);
            TC_WAIT_LD();
            #pragma unroll
            for (int j = 0; j < 32; j += 4) {
                float4 o;
                o.x = __uint_as_float(r[j + 0]) * inv;
                o.y = __uint_as_float(r[j + 1]) * inv;
                o.z = __uint_as_float(r[j + 2]) * inv;
                o.w = __uint_as_float(r[j + 3]) * inv;
                *(float4*)&ob[ch * 32 + j] = o;
            }
        }
    }
    __syncthreads();
    if (wid == 0) {
        if (elect_one()) { MBAR_INVAL(smb + SM_M1); MBAR_INVAL(smb + SM_M2); }
        TC_DEALLOC(tmem, 512);
    }
#endif  // TC_OK
}

// ---------------------------------------------------------------------------
extern "C" void kernel_launch(void* const* d_in, const int* in_sizes, int n_in,
                              void* d_out, int out_size)
{
    const float* x  = (const float*)d_in[0];
    const float* Wq = (const float*)d_in[1];
    const float* bq = (const float*)d_in[2];
    const float* Wk = (const float*)d_in[3];
    const float* bk = (const float*)d_in[4];
    const float* Wv = (const float*)d_in[5];
    const float* bv = (const float*)d_in[6];
    float* out = (float*)d_out;

    dim3 gproj(NTOK / 64, EMB / 64, BATCH * 3);
    qkv_proj_kernel<<<gproj, 256>>>(x, Wq, bq, Wk, bk, Wv, bv);

    cudaFuncAttributes fa;
    fa.numRegs = 0;
    cudaFuncGetAttributes(&fa, (const void*)attn_tc_kernel);

    if (fa.numRegs > 40) {
        cudaFuncSetAttribute(attn_tc_kernel,
                             cudaFuncAttributeMaxDynamicSharedMemorySize,
                             ATT_TC_SMEM);
        dim3 gatt(NTOK / TCQ, BATCH);
        attn_tc_kernel<<<gatt, 256, ATT_TC_SMEM>>>(out);
    } else {
        cudaFuncSetAttribute(attn_simt_kernel,
                             cudaFuncAttributeMaxDynamicSharedMemorySize,
                             ATT_SMEM_BYTES);
        dim3 gatt(NTOK / SQBLK, BATCH);
        attn_simt_kernel<<<gatt, 256, ATT_SMEM_BYTES>>>(out);
    }
}

// round 9
// speedup vs baseline: 1.6394x; 1.6394x over previous
#include <cuda_runtime.h>
#include <cuda_bf16.h>
#include <cstdint>

#define BATCH 4
#define EMB   256
#define NTOK  4096
#define NITER_TC (NTOK / 64)
#define LOG2E 1.4426950408889634f

__device__ float g_q [(size_t)BATCH * NTOK * EMB];
__device__ float g_k [(size_t)BATCH * NTOK * EMB];
__device__ __nv_bfloat16 g_vt[(size_t)BATCH * EMB * NTOK];

#if defined(__CUDA_ARCH_FEAT_SM103_ALL) || defined(__CUDA_ARCH_FEAT_SM100_ALL) || \
    defined(__CUDA_ARCH_FEAT_SM101_ALL) || defined(__CUDA_ARCH_SPECIFIC__)
#define TC_OK 1
#else
#define TC_OK 0
#endif

#if TC_OK
__device__ __forceinline__ uint32_t smem_u32(const void* p) {
    uint32_t a;
    asm("{ .reg .u64 t; cvta.to.shared.u64 t, %1; cvt.u32.u64 %0, t; }"
        : "=r"(a) : "l"(p));
    return a;
}
__device__ __forceinline__ uint32_t elect_one() {
    uint32_t pred;
    asm volatile("{\n\t.reg .pred p;\n\telect.sync _|p, 0xFFFFFFFF;\n\t"
                 "selp.b32 %0, 1, 0, p;\n\t}" : "=r"(pred));
    return pred;
}
__device__ __forceinline__ float f2tf32(float f) {
    uint32_t u;
    asm("cvt.rna.tf32.f32 %0, %1;" : "=r"(u) : "f"(f));
    return __uint_as_float(u);
}

#define MBAR_INIT(mbar, cnt) \
    asm volatile("mbarrier.init.shared.b64 [%0], %1;" :: "r"(mbar), "r"(cnt) : "memory")
#define MBAR_INVAL(mbar) \
    asm volatile("mbarrier.inval.shared.b64 [%0];" :: "r"(mbar) : "memory")
#define MBAR_WAIT(mbar, parity) do {                                             \
    uint32_t _mb = (mbar); uint32_t _ph = (parity); uint32_t _done;              \
    asm volatile("{\n\t.reg .pred p;\n\t"                                        \
        "mbarrier.try_wait.parity.acquire.cta.shared::cta.b64 p, [%1], %2;\n\t"  \
        "selp.b32 %0, 1, 0, p;\n\t}"                                             \
        : "=r"(_done) : "r"(_mb), "r"(_ph) : "memory");                          \
    if (!_done) {                                                                \
        asm volatile("{\n\t.reg .pred P1;\n\t"                                   \
            "WL_%=:\n\t"                                                         \
            "mbarrier.try_wait.parity.acquire.cta.shared::cta.b64 P1, [%0], %1, 0x989680;\n\t" \
            "@P1 bra.uni WD_%=;\n\t"                                             \
            "bra.uni WL_%=;\n\t"                                                 \
            "WD_%=:\n\t}" :: "r"(_mb), "r"(_ph) : "memory");                     \
    }                                                                            \
} while (0)

#define TC_ALLOC(dst_smem, ncols) \
    asm volatile("tcgen05.alloc.cta_group::1.sync.aligned.shared::cta.b32 [%0], %1;" \
                 :: "r"(dst_smem), "r"(ncols) : "memory")
#define TC_RELINQ() \
    asm volatile("tcgen05.relinquish_alloc_permit.cta_group::1.sync.aligned;")
#define TC_DEALLOC(tmem, ncols) \
    asm volatile("tcgen05.dealloc.cta_group::1.sync.aligned.b32 %0, %1;" \
                 :: "r"(tmem), "r"(ncols))
#define TC_COMMIT(mbar) \
    asm volatile("tcgen05.commit.cta_group::1.mbarrier::arrive::one.shared::cluster.b64 [%0];" \
                 :: "r"(mbar) : "memory")
#define TC_WAIT_LD()  asm volatile("tcgen05.wait::ld.sync.aligned;"  ::: "memory")
#define TC_WAIT_ST()  asm volatile("tcgen05.wait::st.sync.aligned;"  ::: "memory")
#define TC_FENCE_BEFORE() asm volatile("tcgen05.fence::before_thread_sync;" ::: "memory")
#define TC_FENCE_AFTER()  asm volatile("tcgen05.fence::after_thread_sync;"  ::: "memory")
#define FENCE_ASYNC_SHARED() asm volatile("fence.proxy.async.shared::cta;" ::: "memory")

#define LDTM_X32(r, addr) \
    asm volatile("tcgen05.ld.sync.aligned.32x32b.x32.b32 " \
        "{%0, %1, %2, %3, %4, %5, %6, %7, %8, %9, %10, %11, %12, %13, %14, %15, " \
        " %16, %17, %18, %19, %20, %21, %22, %23, %24, %25, %26, %27, %28, %29, %30, %31}, [%32];" \
        : "=r"((r)[0]),  "=r"((r)[1]),  "=r"((r)[2]),  "=r"((r)[3]),  \
          "=r"((r)[4]),  "=r"((r)[5]),  "=r"((r)[6]),  "=r"((r)[7]),  \
          "=r"((r)[8]),  "=r"((r)[9]),  "=r"((r)[10]), "=r"((r)[11]), \
          "=r"((r)[12]), "=r"((r)[13]), "=r"((r)[14]), "=r"((r)[15]), \
          "=r"((r)[16]), "=r"((r)[17]), "=r"((r)[18]), "=r"((r)[19]), \
          "=r"((r)[20]), "=r"((r)[21]), "=r"((r)[22]), "=r"((r)[23]), \
          "=r"((r)[24]), "=r"((r)[25]), "=r"((r)[26]), "=r"((r)[27]), \
          "=r"((r)[28]), "=r"((r)[29]), "=r"((r)[30]), "=r"((r)[31]) \
        : "r"(addr))

#define STTM_X16(addr, r) \
    asm volatile("tcgen05.st.sync.aligned.32x32b.x16.b32 [%0], " \
        "{%1, %2, %3, %4, %5, %6, %7, %8, %9, %10, %11, %12, %13, %14, %15, %16};" \
        :: "r"(addr), \
           "r"((r)[0]),  "r"((r)[1]),  "r"((r)[2]),  "r"((r)[3]),  \
           "r"((r)[4]),  "r"((r)[5]),  "r"((r)[6]),  "r"((r)[7]),  \
           "r"((r)[8]),  "r"((r)[9]),  "r"((r)[10]), "r"((r)[11]), \
           "r"((r)[12]), "r"((r)[13]), "r"((r)[14]), "r"((r)[15]) \
        : "memory")

__device__ __forceinline__ uint64_t make_desc(uint32_t smem_addr) {
    return 0x4000404000010000ULL | ((uint64_t)(smem_addr >> 4) & 0x3FFF);
}
__device__ __forceinline__ void mma_tf32_ss(uint32_t d, uint64_t a, uint64_t b,
                                            uint32_t idesc, uint32_t en) {
    asm volatile("{\n\t.reg .pred p;\n\tsetp.ne.u32 p, %5, 0;\n\t"
        "tcgen05.mma.cta_group::1.kind::tf32 [%0], %1, %2, %3, {%4, %4, %4, %4}, p;\n\t}"
        :: "r"(d), "l"(a), "l"(b), "r"(idesc), "r"(0u), "r"(en) : "memory");
}
__device__ __forceinline__ void mma_f16_ts(uint32_t d, uint32_t a, uint64_t b,
                                           uint32_t idesc, uint32_t en) {
    asm volatile("{\n\t.reg .pred p;\n\tsetp.ne.u32 p, %5, 0;\n\t"
        "tcgen05.mma.cta_group::1.kind::f16 [%0], [%1], %2, %3, {%4, %4, %4, %4}, p;\n\t}"
        :: "r"(d), "r"(a), "l"(b), "r"(idesc), "r"(0u), "r"(en) : "memory");
}
__device__ __forceinline__ uint32_t sw128(uint32_t b) { return b ^ ((b >> 3) & 0x70); }
#endif  // TC_OK

// ============================================================================
// tcgen05 QKV projection. CTA = (128-token tile, batch), 256 threads.
// A = X^T [128n x 256c] tf32 SW128 (16x8 atoms); B = W chunks [32d x 256c]
// (4x8 atoms), double-buffered; D in TMEM (2 x 256 cols). 24 chunk-MMAs.
// TWO mbarriers (one per W buffer) -> commits/waits strictly alternate per
// barrier, eliminating the parity-aliasing deadlock of R8.
// ============================================================================
#define PSM_X   0
#define PSM_W   131072
#define PSM_PTR 196608
#define PSM_MB  196616     /* two 8-byte mbarriers: +0, +8 */
#define PROJ_SMEM 196640
#define IDESC_P ((1u << 4) | (2u << 7) | (2u << 10) | (4u << 17) | (8u << 24))

__global__ __launch_bounds__(256, 1) void proj_tc_kernel(
    const float* __restrict__ x,
    const float* __restrict__ Wq, const float* __restrict__ bq,
    const float* __restrict__ Wk, const float* __restrict__ bk,
    const float* __restrict__ Wv, const float* __restrict__ bv)
{
#if TC_OK
    extern __shared__ char sm[];
    const uint32_t smb = smem_u32(sm);
    const int tid = threadIdx.x;
    const int wid = tid >> 5;
    const int sp  = wid & 3;
    const int wg  = wid >> 2;
    const int lid = tid & 31;
    const int n0  = blockIdx.x * 128;
    const int b   = blockIdx.y;

    if (wid == 0) {
        TC_ALLOC(smb + PSM_PTR, 512);
        TC_RELINQ();
        if (elect_one()) {
            MBAR_INIT(smb + PSM_MB + 0, 1);
            MBAR_INIT(smb + PSM_MB + 8, 1);
        }
    }
    __syncthreads();
    uint32_t tmem;
    asm volatile("ld.shared.b32 %0, [%1];" : "=r"(tmem) : "r"(smb + PSM_PTR));
    const uint32_t woff = (uint32_t)sp << 21;
    const int n = sp * 32 + lid;

    // ---- prologue: X^T tile. read x[b][c][n0..n0+128) coalesced over n ----
    {
        const float* xb = x + (size_t)b * EMB * NTOK + n0;
        #pragma unroll 8
        for (int it = 0; it < 32; ++it) {
            const int idx = tid + it * 256;
            const int c   = idx >> 5;
            const int nc4 = idx & 31;
            float4 v = *(const float4*)&xb[(size_t)c * NTOK + nc4 * 4];
            const uint32_t cb = (uint32_t)((c >> 5) * 16384 + ((c >> 2) & 7) * 16 + (c & 3) * 4);
            #pragma unroll
            for (int k2 = 0; k2 < 4; ++k2) {
                const int nn = nc4 * 4 + k2;
                uint32_t byte = cb + (uint32_t)((nn >> 3) * 1024 + (nn & 7) * 128);
                *(float*)(sm + PSM_X + sw128(byte)) =
                    f2tf32(k2 == 0 ? v.x : k2 == 1 ? v.y : k2 == 2 ? v.z : v.w);
            }
        }
    }

    const uint64_t xdesc = make_desc(smb + PSM_X);
    const float* Ws[3] = { Wq, Wk, Wv };
    int php[2] = { 0, 0 };

    for (int i = 0; i < 24; ++i) {
        const int bi = i & 1;

        // wait MMA(i-2) on this buffer's barrier (strictly alternating per barrier)
        if (i >= 2) { MBAR_WAIT(smb + PSM_MB + bi * 8, php[bi]); php[bi] ^= 1; }

        // epilogue(q) at i==16: commits 0..14 are done (wait above covered 14),
        // so D cols 0..255 (matrix q, commits 0..7) are final.
        if (i == 16) {
            TC_FENCE_AFTER();
            const float scl = 0.0625f * LOG2E;
            float* dst0 = g_q + ((size_t)b * NTOK + n0 + n) * EMB;
            #pragma unroll
            for (int cc = 0; cc < 4; ++cc) {
                const int col0 = wg * 128 + cc * 32;
                uint32_t r[32];
                LDTM_X32(r, tmem + (uint32_t)col0 + woff);
                TC_WAIT_LD();
                #pragma unroll
                for (int j = 0; j < 32; j += 4) {
                    float4 o;
                    o.x = f2tf32((__uint_as_float(r[j+0]) + __ldg(&bq[col0+j+0])) * scl);
                    o.y = f2tf32((__uint_as_float(r[j+1]) + __ldg(&bq[col0+j+1])) * scl);
                    o.z = f2tf32((__uint_as_float(r[j+2]) + __ldg(&bq[col0+j+2])) * scl);
                    o.w = f2tf32((__uint_as_float(r[j+3]) + __ldg(&bq[col0+j+3])) * scl);
                    *(float4*)&dst0[col0 + j] = o;
                }
            }
            TC_FENCE_BEFORE();
            __syncthreads();
        }

        // load W chunk i into buffer bi (rows = 32 d, cols = 256 c; 4x8 atoms)
        {
            const float* W = Ws[i >> 3] + (size_t)((i & 7) * 32) * EMB;
            char* buf = sm + PSM_W + bi * 32768;
            #pragma unroll
            for (int it = 0; it < 8; ++it) {
                const int idx = tid + it * 256;
                const int r  = idx >> 6;
                const int c4 = idx & 63;
                float4 v = *(const float4*)&W[(size_t)r * EMB + c4 * 4];
                v.x = f2tf32(v.x); v.y = f2tf32(v.y);
                v.z = f2tf32(v.z); v.w = f2tf32(v.w);
                uint32_t byte = (uint32_t)(((r >> 3) + (c4 >> 3) * 4) * 1024
                                           + (r & 7) * 128 + (c4 & 7) * 16);
                *(float4*)(buf + sw128(byte)) = v;
            }
        }
        FENCE_ASYNC_SHARED();
        __syncthreads();

        if (wid == 0) {
            TC_FENCE_AFTER();
            if (elect_one()) {
                const uint64_t wd = make_desc(smb + PSM_W + (uint32_t)(bi * 32768));
                const uint32_t dtm = tmem + (uint32_t)(((i >> 3) == 1 ? 256 : 0) + (i & 7) * 32);
                #pragma unroll
                for (int s = 0; s < 32; ++s) {
                    mma_tf32_ss(dtm, xdesc + (uint64_t)((s >> 2) * 1024 + (s & 3) * 2),
                                     wd    + (uint64_t)((s >> 2) * 256  + (s & 3) * 2),
                                IDESC_P, (uint32_t)(s > 0));
                }
                TC_COMMIT(smb + PSM_MB + bi * 8);
            }
        }
    }
    // drain: commits 22 (mb0) and 23 (mb1) outstanding
    MBAR_WAIT(smb + PSM_MB + 0, php[0]); php[0] ^= 1;
    MBAR_WAIT(smb + PSM_MB + 8, php[1]); php[1] ^= 1;
    TC_FENCE_AFTER();

    // epilogue k (D cols 256..511)
    {
        float* dst = g_k + ((size_t)b * NTOK + n0 + n) * EMB;
        #pragma unroll
        for (int cc = 0; cc < 4; ++cc) {
            const int col0 = wg * 128 + cc * 32;
            uint32_t r[32];
            LDTM_X32(r, tmem + (uint32_t)(256 + col0) + woff);
            TC_WAIT_LD();
            #pragma unroll
            for (int j = 0; j < 32; j += 4) {
                float4 o;
                o.x = f2tf32(__uint_as_float(r[j+0]) + __ldg(&bk[col0+j+0]));
                o.y = f2tf32(__uint_as_float(r[j+1]) + __ldg(&bk[col0+j+1]));
                o.z = f2tf32(__uint_as_float(r[j+2]) + __ldg(&bk[col0+j+2]));
                o.w = f2tf32(__uint_as_float(r[j+3]) + __ldg(&bk[col0+j+3]));
                *(float4*)&dst[col0 + j] = o;
            }
        }
    }
    // epilogue v -> g_vt[d][n] bf16 (coalesced over n within each warp)
    {
        __nv_bfloat16* vt = g_vt + (size_t)b * EMB * NTOK + n0 + n;
        #pragma unroll
        for (int cc = 0; cc < 4; ++cc) {
            const int col0 = wg * 128 + cc * 32;
            uint32_t r[32];
            LDTM_X32(r, tmem + (uint32_t)col0 + woff);
            TC_WAIT_LD();
            #pragma unroll
            for (int j = 0; j < 32; ++j) {
                const float v = __uint_as_float(r[j]) + __ldg(&bv[col0 + j]);
                vt[(size_t)(col0 + j) * NTOK] = __float2bfloat16(v);
            }
        }
    }
    __syncthreads();
    if (wid == 0) {
        if (elect_one()) { MBAR_INVAL(smb + PSM_MB + 0); MBAR_INVAL(smb + PSM_MB + 8); }
        TC_DEALLOC(tmem, 512);
    }
#endif
}

// ============================================================================
// tcgen05 pipelined attention (unchanged from R6 best; 253us).
// ============================================================================
#define TCQ 128
#define TCK 64
#define SM_Q    0
#define SM_K    131072
#define SM_V    196608
#define SM_PTR  229376
#define SM_M1   229384
#define SM_M2   229392
#define SM_L    229408
#define ATT_TC_SMEM (229408 + 2 * 128 * 4)
#define TM_S 0
#define TM_P 128
#define TM_O 256
#define IDESC1 ((1u << 4) | (2u << 7) | (2u << 10) | ((TCK / 8) << 17) | ((TCQ / 16) << 24))
#define IDESC2 ((1u << 4) | (1u << 7) | (1u << 10) | ((EMB / 8) << 17) | ((TCQ / 16) << 24))

#if TC_OK
__device__ __forceinline__ void load_k_tile(char* sm, const float* gk, int tid) {
    #pragma unroll 8
    for (int it = 0; it < 16; ++it) {
        const int idx = tid + it * 256;
        const int r  = idx >> 6;
        const int c4 = idx & 63;
        float4 v = *(const float4*)&gk[(size_t)r * EMB + c4 * 4];
        uint32_t byte = (uint32_t)(((r >> 3) + (c4 >> 3) * 8) * 1024
                                   + (r & 7) * 128 + (c4 & 7) * 16);
        *(float4*)(sm + SM_K + sw128(byte)) = v;
    }
}
__device__ __forceinline__ void issue_mma1(uint32_t sdst, uint64_t qdesc,
                                           uint64_t kdesc, uint32_t mbar) {
    #pragma unroll
    for (int s = 0; s < 32; ++s) {
        mma_tf32_ss(sdst, qdesc + (uint64_t)((s >> 2) * 1024 + (s & 3) * 2),
                          kdesc + (uint64_t)((s >> 2) * 512  + (s & 3) * 2),
                    IDESC1, (uint32_t)(s > 0));
    }
    TC_COMMIT(mbar);
}
#endif

__global__ __launch_bounds__(256, 1) void attn_tc_kernel(float* __restrict__ out)
{
#if TC_OK
    extern __shared__ char sm[];
    const uint32_t smb = smem_u32(sm);
    const int tid = threadIdx.x;
    const int wid = tid >> 5;
    const int sp  = wid & 3;
    const int wg  = wid >> 2;
    const int lid = tid & 31;
    const int q0  = blockIdx.x * TCQ;
    const int b   = blockIdx.y;

    if (wid == 0) {
        TC_ALLOC(smb + SM_PTR, 512);
        TC_RELINQ();
        if (elect_one()) { MBAR_INIT(smb + SM_M1, 1); MBAR_INIT(smb + SM_M2, 1); }
    }
    __syncthreads();
    uint32_t tmem;
    asm volatile("ld.shared.b32 %0, [%1];" : "=r"(tmem) : "r"(smb + SM_PTR));
    const uint32_t woff = (uint32_t)sp << 21;

    const uint64_t qdesc = make_desc(smb + SM_Q);
    const uint64_t kdesc = make_desc(smb + SM_K);
    const uint64_t vdesc = make_desc(smb + SM_V);

    {
        const float* gq = g_q + ((size_t)b * NTOK + q0) * EMB;
        #pragma unroll 8
        for (int it = 0; it < 32; ++it) {
            const int idx = tid + it * 256;
            const int r  = idx >> 6;
            const int c4 = idx & 63;
            float4 v = *(const float4*)&gq[(size_t)r * EMB + c4 * 4];
            uint32_t byte = (uint32_t)(((r >> 3) + (c4 >> 3) * 16) * 1024
                                       + (r & 7) * 128 + (c4 & 7) * 16);
            *(float4*)(sm + SM_Q + sw128(byte)) = v;
        }
        load_k_tile(sm, g_k + (size_t)b * NTOK * EMB, tid);
    }
    FENCE_ASYNC_SHARED();
    __syncthreads();
    if (wid == 0) {
        TC_FENCE_AFTER();
        if (elect_one()) issue_mma1(tmem + TM_S, qdesc, kdesc, smb + SM_M1);
    }

    float lsum = 0.f;
    int ph1 = 0, ph2 = 0;

    for (int itn = 0; itn < NITER_TC; ++itn) {
        const int k0 = itn * TCK;

        MBAR_WAIT(smb + SM_M1, ph1); ph1 ^= 1;
        TC_FENCE_AFTER();

        if (itn < NITER_TC - 1) {
            load_k_tile(sm, g_k + ((size_t)b * NTOK + k0 + TCK) * EMB, tid);
            FENCE_ASYNC_SHARED();
            __syncthreads();
            if (wid == 0) {
                TC_FENCE_AFTER();
                if (elect_one())
                    issue_mma1(tmem + TM_S + (uint32_t)(((itn + 1) & 1) << 6),
                               qdesc, kdesc, smb + SM_M1);
            }
        }

        uint32_t pr[16];
        {
            const uint32_t sbase = tmem + TM_S + (uint32_t)((itn & 1) << 6)
                                 + (uint32_t)(wg << 5) + woff;
            uint32_t sreg[32];
            LDTM_X32(sreg, sbase);
            TC_WAIT_LD();
            float part = 0.f;
            #pragma unroll
            for (int j = 0; j < 16; ++j) {
                const float p0 = exp2f(__uint_as_float(sreg[2 * j]));
                const float p1 = exp2f(__uint_as_float(sreg[2 * j + 1]));
                part += p0 + p1;
                asm("cvt.rn.bf16x2.f32 %0, %1, %2;" : "=r"(pr[j]) : "f"(p1), "f"(p0));
            }
            lsum += part;
        }

        if (itn > 0) { MBAR_WAIT(smb + SM_M2, ph2); ph2 ^= 1; }
        TC_FENCE_AFTER();

        {
            const __nv_bfloat16* gvt = g_vt + (size_t)b * EMB * NTOK + k0;
            #pragma unroll 8
            for (int it = 0; it < 8; ++it) {
                const int idx = tid + it * 256;
                const int r = idx >> 3;
                const int c = idx & 7;
                uint4 v = *(const uint4*)&gvt[(size_t)r * NTOK + c * 8];
                uint32_t byte = (uint32_t)((r >> 3) * 1024 + (r & 7) * 128 + c * 16);
                *(uint4*)(sm + SM_V + sw128(byte)) = v;
            }
            STTM_X16(tmem + TM_P + (uint32_t)(wg << 4) + woff, pr);
            TC_WAIT_ST();
        }
        TC_FENCE_BEFORE();
        FENCE_ASYNC_SHARED();
        __syncthreads();
        if (wid == 0) {
            TC_FENCE_AFTER();
            if (elect_one()) {
                #pragma unroll
                for (int s = 0; s < 4; ++s) {
                    mma_f16_ts(tmem + TM_O, tmem + TM_P + s * 8,
                               vdesc + (uint64_t)(s * 2), IDESC2,
                               (uint32_t)((itn > 0) | (s > 0)));
                }
                TC_COMMIT(smb + SM_M2);
            }
        }
    }

    MBAR_WAIT(smb + SM_M2, ph2); ph2 ^= 1;
    TC_FENCE_AFTER();
    {
        float* lpart = (float*)(sm + SM_L);
        const int row = sp * 32 + lid;
        lpart[wg * 128 + row] = lsum;
        __syncthreads();
        const float inv = 1.f / (lpart[row] + lpart[128 + row]);

        float* ob = out + ((size_t)b * NTOK + q0 + row) * EMB + wg * 128;
        #pragma unroll
        for (int ch = 0; ch < 4; ++ch) {
            uint32_t r[32];
            LDTM_X32(r, tmem + TM_O + (uint32_t)(wg * 128 + ch * 32) + woff);
            TC_WAIT_LD();
            #pragma unroll
            for (int j = 0; j < 32; j += 4) {
                float4 o;
                o.x = __uint_as_float(r[j + 0]) * inv;
                o.y = __uint_as_float(r[j + 1]) * inv;
                o.z = __uint_as_float(r[j + 2]) * inv;
                o.w = __uint_as_float(r[j + 3]) * inv;
                *(float4*)&ob[ch * 32 + j] = o;
            }
        }
    }
    __syncthreads();
    if (wid == 0) {
        if (elect_one()) { MBAR_INVAL(smb + SM_M1); MBAR_INVAL(smb + SM_M2); }
        TC_DEALLOC(tmem, 512);
    }
#endif
}

// ---------------------------------------------------------------------------
extern "C" void kernel_launch(void* const* d_in, const int* in_sizes, int n_in,
                              void* d_out, int out_size)
{
    const float* x  = (const float*)d_in[0];
    const float* Wq = (const float*)d_in[1];
    const float* bq = (const float*)d_in[2];
    const float* Wk = (const float*)d_in[3];
    const float* bk = (const float*)d_in[4];
    const float* Wv = (const float*)d_in[5];
    const float* bv = (const float*)d_in[6];
    float* out = (float*)d_out;

    cudaFuncSetAttribute(proj_tc_kernel,
                         cudaFuncAttributeMaxDynamicSharedMemorySize, PROJ_SMEM);
    cudaFuncSetAttribute(attn_tc_kernel,
                         cudaFuncAttributeMaxDynamicSharedMemorySize, ATT_TC_SMEM);

    dim3 gproj(NTOK / 128, BATCH);
    proj_tc_kernel<<<gproj, 256, PROJ_SMEM>>>(x, Wq, bq, Wk, bk, Wv, bv);

    dim3 gatt(NTOK / TCQ, BATCH);
    attn_tc_kernel<<<gatt, 256, ATT_TC_SMEM>>>(out);
}

// round 11
// speedup vs baseline: 2.5115x; 1.5319x over previous
#include <cuda_runtime.h>
#include <cuda_fp16.h>
#include <cstdint>

#define BATCH 4
#define EMB   256
#define NTOK  4096
#define TCK   128
#define NITER (NTOK / TCK)
#define LOG2E 1.4426950408889634f

__device__ __half g_q [(size_t)BATCH * NTOK * EMB];
__device__ __half g_k [(size_t)BATCH * NTOK * EMB];
__device__ __half g_vt[(size_t)BATCH * EMB * NTOK];

#if defined(__CUDA_ARCH_FEAT_SM103_ALL) || defined(__CUDA_ARCH_FEAT_SM100_ALL) || \
    defined(__CUDA_ARCH_FEAT_SM101_ALL) || defined(__CUDA_ARCH_SPECIFIC__)
#define TC_OK 1
#else
#define TC_OK 0
#endif

#if TC_OK
__device__ __forceinline__ uint32_t smem_u32(const void* p) {
    uint32_t a;
    asm("{ .reg .u64 t; cvta.to.shared.u64 t, %1; cvt.u32.u64 %0, t; }"
        : "=r"(a) : "l"(p));
    return a;
}
__device__ __forceinline__ uint32_t elect_one() {
    uint32_t pred;
    asm volatile("{\n\t.reg .pred p;\n\telect.sync _|p, 0xFFFFFFFF;\n\t"
                 "selp.b32 %0, 1, 0, p;\n\t}" : "=r"(pred));
    return pred;
}
__device__ __forceinline__ float f2tf32(float f) {
    uint32_t u;
    asm("cvt.rna.tf32.f32 %0, %1;" : "=r"(u) : "f"(f));
    return __uint_as_float(u);
}

#define MBAR_INIT(mbar, cnt) \
    asm volatile("mbarrier.init.shared.b64 [%0], %1;" :: "r"(mbar), "r"(cnt) : "memory")
#define MBAR_INVAL(mbar) \
    asm volatile("mbarrier.inval.shared.b64 [%0];" :: "r"(mbar) : "memory")
#define MBAR_WAIT(mbar, parity) do {                                             \
    uint32_t _mb = (mbar); uint32_t _ph = (parity); uint32_t _done;              \
    asm volatile("{\n\t.reg .pred p;\n\t"                                        \
        "mbarrier.try_wait.parity.acquire.cta.shared::cta.b64 p, [%1], %2;\n\t"  \
        "selp.b32 %0, 1, 0, p;\n\t}"                                             \
        : "=r"(_done) : "r"(_mb), "r"(_ph) : "memory");                          \
    if (!_done) {                                                                \
        asm volatile("{\n\t.reg .pred P1;\n\t"                                   \
            "WL_%=:\n\t"                                                         \
            "mbarrier.try_wait.parity.acquire.cta.shared::cta.b64 P1, [%0], %1, 0x989680;\n\t" \
            "@P1 bra.uni WD_%=;\n\t"                                             \
            "bra.uni WL_%=;\n\t"                                                 \
            "WD_%=:\n\t}" :: "r"(_mb), "r"(_ph) : "memory");                     \
    }                                                                            \
} while (0)

#define TC_ALLOC(dst_smem, ncols) \
    asm volatile("tcgen05.alloc.cta_group::1.sync.aligned.shared::cta.b32 [%0], %1;" \
                 :: "r"(dst_smem), "r"(ncols) : "memory")
#define TC_RELINQ() \
    asm volatile("tcgen05.relinquish_alloc_permit.cta_group::1.sync.aligned;")
#define TC_DEALLOC(tmem, ncols) \
    asm volatile("tcgen05.dealloc.cta_group::1.sync.aligned.b32 %0, %1;" \
                 :: "r"(tmem), "r"(ncols))
#define TC_COMMIT(mbar) \
    asm volatile("tcgen05.commit.cta_group::1.mbarrier::arrive::one.shared::cluster.b64 [%0];" \
                 :: "r"(mbar) : "memory")
#define TC_WAIT_LD()  asm volatile("tcgen05.wait::ld.sync.aligned;"  ::: "memory")
#define TC_WAIT_ST()  asm volatile("tcgen05.wait::st.sync.aligned;"  ::: "memory")
#define TC_FENCE_BEFORE() asm volatile("tcgen05.fence::before_thread_sync;" ::: "memory")
#define TC_FENCE_AFTER()  asm volatile("tcgen05.fence::after_thread_sync;"  ::: "memory")
#define FENCE_ASYNC_SHARED() asm volatile("fence.proxy.async.shared::cta;" ::: "memory")

#define LDTM_X32(r, addr) \
    asm volatile("tcgen05.ld.sync.aligned.32x32b.x32.b32 " \
        "{%0, %1, %2, %3, %4, %5, %6, %7, %8, %9, %10, %11, %12, %13, %14, %15, " \
        " %16, %17, %18, %19, %20, %21, %22, %23, %24, %25, %26, %27, %28, %29, %30, %31}, [%32];" \
        : "=r"((r)[0]),  "=r"((r)[1]),  "=r"((r)[2]),  "=r"((r)[3]),  \
          "=r"((r)[4]),  "=r"((r)[5]),  "=r"((r)[6]),  "=r"((r)[7]),  \
          "=r"((r)[8]),  "=r"((r)[9]),  "=r"((r)[10]), "=r"((r)[11]), \
          "=r"((r)[12]), "=r"((r)[13]), "=r"((r)[14]), "=r"((r)[15]), \
          "=r"((r)[16]), "=r"((r)[17]), "=r"((r)[18]), "=r"((r)[19]), \
          "=r"((r)[20]), "=r"((r)[21]), "=r"((r)[22]), "=r"((r)[23]), \
          "=r"((r)[24]), "=r"((r)[25]), "=r"((r)[26]), "=r"((r)[27]), \
          "=r"((r)[28]), "=r"((r)[29]), "=r"((r)[30]), "=r"((r)[31]) \
        : "r"(addr))

#define STTM_X16(addr, r) \
    asm volatile("tcgen05.st.sync.aligned.32x32b.x16.b32 [%0], " \
        "{%1, %2, %3, %4, %5, %6, %7, %8, %9, %10, %11, %12, %13, %14, %15, %16};" \
        :: "r"(addr), \
           "r"((r)[0]),  "r"((r)[1]),  "r"((r)[2]),  "r"((r)[3]),  \
           "r"((r)[4]),  "r"((r)[5]),  "r"((r)[6]),  "r"((r)[7]),  \
           "r"((r)[8]),  "r"((r)[9]),  "r"((r)[10]), "r"((r)[11]), \
           "r"((r)[12]), "r"((r)[13]), "r"((r)[14]), "r"((r)[15]) \
        : "memory")

__device__ __forceinline__ uint64_t make_desc(uint32_t smem_addr) {
    return 0x4000404000010000ULL | ((uint64_t)(smem_addr >> 4) & 0x3FFF);
}
__device__ __forceinline__ void mma_tf32_ss(uint32_t d, uint64_t a, uint64_t b,
                                            uint32_t idesc, uint32_t en) {
    asm volatile("{\n\t.reg .pred p;\n\tsetp.ne.u32 p, %5, 0;\n\t"
        "tcgen05.mma.cta_group::1.kind::tf32 [%0], %1, %2, %3, {%4, %4, %4, %4}, p;\n\t}"
        :: "r"(d), "l"(a), "l"(b), "r"(idesc), "r"(0u), "r"(en) : "memory");
}
__device__ __forceinline__ void mma_f16_ss(uint32_t d, uint64_t a, uint64_t b,
                                           uint32_t idesc, uint32_t en) {
    asm volatile("{\n\t.reg .pred p;\n\tsetp.ne.u32 p, %5, 0;\n\t"
        "tcgen05.mma.cta_group::1.kind::f16 [%0], %1, %2, %3, {%4, %4, %4, %4}, p;\n\t}"
        :: "r"(d), "l"(a), "l"(b), "r"(idesc), "r"(0u), "r"(en) : "memory");
}
__device__ __forceinline__ void mma_f16_ts(uint32_t d, uint32_t a, uint64_t b,
                                           uint32_t idesc, uint32_t en) {
    asm volatile("{\n\t.reg .pred p;\n\tsetp.ne.u32 p, %5, 0;\n\t"
        "tcgen05.mma.cta_group::1.kind::f16 [%0], [%1], %2, %3, {%4, %4, %4, %4}, p;\n\t}"
        :: "r"(d), "r"(a), "l"(b), "r"(idesc), "r"(0u), "r"(en) : "memory");
}
__device__ __forceinline__ uint32_t sw128(uint32_t b) { return b ^ ((b >> 3) & 0x70); }
#endif  // TC_OK

// ============================================================================
// tcgen05 QKV projection (R9 WIN structure; fp16 outputs).
// ============================================================================
#define PSM_X   0
#define PSM_W   131072
#define PSM_PTR 196608
#define PSM_MB  196616
#define PROJ_SMEM 196640
#define IDESC_P ((1u << 4) | (2u << 7) | (2u << 10) | (4u << 17) | (8u << 24))

__global__ __launch_bounds__(256, 1) void proj_tc_kernel(
    const float* __restrict__ x,
    const float* __restrict__ Wq, const float* __restrict__ bq,
    const float* __restrict__ Wk, const float* __restrict__ bk,
    const float* __restrict__ Wv, const float* __restrict__ bv)
{
#if TC_OK
    extern __shared__ char sm[];
    const uint32_t smb = smem_u32(sm);
    const int tid = threadIdx.x;
    const int wid = tid >> 5;
    const int sp  = wid & 3;
    const int wg  = wid >> 2;
    const int lid = tid & 31;
    const int n0  = blockIdx.x * 128;
    const int b   = blockIdx.y;

    if (wid == 0) {
        TC_ALLOC(smb + PSM_PTR, 512);
        TC_RELINQ();
        if (elect_one()) {
            MBAR_INIT(smb + PSM_MB + 0, 1);
            MBAR_INIT(smb + PSM_MB + 8, 1);
        }
    }
    __syncthreads();
    uint32_t tmem;
    asm volatile("ld.shared.b32 %0, [%1];" : "=r"(tmem) : "r"(smb + PSM_PTR));
    const uint32_t woff = (uint32_t)sp << 21;
    const int n = sp * 32 + lid;

    {
        const float* xb = x + (size_t)b * EMB * NTOK + n0;
        #pragma unroll 8
        for (int it = 0; it < 32; ++it) {
            const int idx = tid + it * 256;
            const int c   = idx >> 5;
            const int nc4 = idx & 31;
            float4 v = *(const float4*)&xb[(size_t)c * NTOK + nc4 * 4];
            const uint32_t cb = (uint32_t)((c >> 5) * 16384 + ((c >> 2) & 7) * 16 + (c & 3) * 4);
            #pragma unroll
            for (int k2 = 0; k2 < 4; ++k2) {
                const int nn = nc4 * 4 + k2;
                uint32_t byte = cb + (uint32_t)((nn >> 3) * 1024 + (nn & 7) * 128);
                *(float*)(sm + PSM_X + sw128(byte)) =
                    f2tf32(k2 == 0 ? v.x : k2 == 1 ? v.y : k2 == 2 ? v.z : v.w);
            }
        }
    }

    const uint64_t xdesc = make_desc(smb + PSM_X);
    const float* Ws[3] = { Wq, Wk, Wv };
    int php[2] = { 0, 0 };

    for (int i = 0; i < 24; ++i) {
        const int bi = i & 1;
        if (i >= 2) { MBAR_WAIT(smb + PSM_MB + bi * 8, php[bi]); php[bi] ^= 1; }

        if (i == 16) {   // epilogue q (D cols 0..255): fp16, prescaled
            TC_FENCE_AFTER();
            const float scl = 0.0625f * LOG2E;
            __half* dst0 = g_q + ((size_t)b * NTOK + n0 + n) * EMB;
            #pragma unroll
            for (int cc = 0; cc < 4; ++cc) {
                const int col0 = wg * 128 + cc * 32;
                uint32_t r[32];
                LDTM_X32(r, tmem + (uint32_t)col0 + woff);
                TC_WAIT_LD();
                #pragma unroll
                for (int j = 0; j < 32; j += 8) {
                    uint32_t w[4];
                    #pragma unroll
                    for (int k2 = 0; k2 < 4; ++k2) {
                        const float v0 = (__uint_as_float(r[j+2*k2+0]) + __ldg(&bq[col0+j+2*k2+0])) * scl;
                        const float v1 = (__uint_as_float(r[j+2*k2+1]) + __ldg(&bq[col0+j+2*k2+1])) * scl;
                        asm("cvt.rn.f16x2.f32 %0, %1, %2;" : "=r"(w[k2]) : "f"(v1), "f"(v0));
                    }
                    uint4 o; o.x = w[0]; o.y = w[1]; o.z = w[2]; o.w = w[3];
                    *(uint4*)&dst0[col0 + j] = o;
                }
            }
            TC_FENCE_BEFORE();
            __syncthreads();
        }

        {
            const float* W = Ws[i >> 3] + (size_t)((i & 7) * 32) * EMB;
            char* buf = sm + PSM_W + bi * 32768;
            #pragma unroll
            for (int it = 0; it < 8; ++it) {
                const int idx = tid + it * 256;
                const int r  = idx >> 6;
                const int c4 = idx & 63;
                float4 v = *(const float4*)&W[(size_t)r * EMB + c4 * 4];
                v.x = f2tf32(v.x); v.y = f2tf32(v.y);
                v.z = f2tf32(v.z); v.w = f2tf32(v.w);
                uint32_t byte = (uint32_t)(((r >> 3) + (c4 >> 3) * 4) * 1024
                                           + (r & 7) * 128 + (c4 & 7) * 16);
                *(float4*)(buf + sw128(byte)) = v;
            }
        }
        FENCE_ASYNC_SHARED();
        __syncthreads();

        if (wid == 0) {
            TC_FENCE_AFTER();
            if (elect_one()) {
                const uint64_t wd = make_desc(smb + PSM_W + (uint32_t)(bi * 32768));
                const uint32_t dtm = tmem + (uint32_t)(((i >> 3) == 1 ? 256 : 0) + (i & 7) * 32);
                #pragma unroll
                for (int s = 0; s < 32; ++s) {
                    mma_tf32_ss(dtm, xdesc + (uint64_t)((s >> 2) * 1024 + (s & 3) * 2),
                                     wd    + (uint64_t)((s >> 2) * 256  + (s & 3) * 2),
                                IDESC_P, (uint32_t)(s > 0));
                }
                TC_COMMIT(smb + PSM_MB + bi * 8);
            }
        }
    }
    MBAR_WAIT(smb + PSM_MB + 0, php[0]); php[0] ^= 1;
    MBAR_WAIT(smb + PSM_MB + 8, php[1]); php[1] ^= 1;
    TC_FENCE_AFTER();

    // epilogue k (D cols 256..511) -> fp16 [n][d]
    {
        __half* dst = g_k + ((size_t)b * NTOK + n0 + n) * EMB;
        #pragma unroll
        for (int cc = 0; cc < 4; ++cc) {
            const int col0 = wg * 128 + cc * 32;
            uint32_t r[32];
            LDTM_X32(r, tmem + (uint32_t)(256 + col0) + woff);
            TC_WAIT_LD();
            #pragma unroll
            for (int j = 0; j < 32; j += 8) {
                uint32_t w[4];
                #pragma unroll
                for (int k2 = 0; k2 < 4; ++k2) {
                    const float v0 = __uint_as_float(r[j+2*k2+0]) + __ldg(&bk[col0+j+2*k2+0]);
                    const float v1 = __uint_as_float(r[j+2*k2+1]) + __ldg(&bk[col0+j+2*k2+1]);
                    asm("cvt.rn.f16x2.f32 %0, %1, %2;" : "=r"(w[k2]) : "f"(v1), "f"(v0));
                }
                uint4 o; o.x = w[0]; o.y = w[1]; o.z = w[2]; o.w = w[3];
                *(uint4*)&dst[col0 + j] = o;
            }
        }
    }
    // epilogue v -> g_vt[d][n] fp16
    {
        __half* vt = g_vt + (size_t)b * EMB * NTOK + n0 + n;
        #pragma unroll
        for (int cc = 0; cc < 4; ++cc) {
            const int col0 = wg * 128 + cc * 32;
            uint32_t r[32];
            LDTM_X32(r, tmem + (uint32_t)col0 + woff);
            TC_WAIT_LD();
            #pragma unroll
            for (int j = 0; j < 32; ++j) {
                const float v = __uint_as_float(r[j]) + __ldg(&bv[col0 + j]);
                vt[(size_t)(col0 + j) * NTOK] = __float2half(v);
            }
        }
    }
    __syncthreads();
    if (wid == 0) {
        if (elect_one()) { MBAR_INVAL(smb + PSM_MB + 0); MBAR_INVAL(smb + PSM_MB + 8); }
        TC_DEALLOC(tmem, 512);
    }
#endif
}

// ============================================================================
// fp16 tcgen05 attention, fp32 S. CTA = (128 q, batch), 512 threads.
// SMEM: Q[128x256]f16 + K[128x256]f16 + V[256x128]f16 = 192KB.
// TMEM: S@0 (128 cols fp32, single buffer), P@128 (64 cols f16x2), O@256 (256).
// Iter: wait MMA1(n) -> LDTM S (frees S) -> load K(n+1), issue MMA1(n+1)
//       -> exp/pack (overlaps MMA1) -> wait MMA2(n-1) -> V load + STTM P
//       -> issue MMA2(n).
// ============================================================================
#define SM_Q   0
#define SM_K   65536
#define SM_V   131072
#define SM_PTR 196608
#define SM_M1  196616
#define SM_M2  196624
#define SM_L   196640
#define ATT_SMEM (196640 + 4 * 128 * 4)
#define TM_S 0
#define TM_P 128
#define TM_O 256
// MMA1: fp16 in, fp32 out, N=128, M=128
#define IDESC1 ((1u << 4) | (16u << 17) | (8u << 24))
// MMA2: fp16 in, fp32 out, N=256, M=128
#define IDESC2 ((1u << 4) | (32u << 17) | (8u << 24))

#if TC_OK
__device__ __forceinline__ void load_qk_tile(char* dst, const __half* g, int tid) {
    #pragma unroll 8
    for (int it = 0; it < 8; ++it) {
        const int idx = tid + it * 512;
        const int r = idx >> 5;
        const int c = idx & 31;
        uint4 v = *(const uint4*)&g[(size_t)r * EMB + c * 8];
        uint32_t byte = (uint32_t)(((r >> 3) + (c >> 3) * 16) * 1024
                                   + (r & 7) * 128 + (c & 7) * 16);
        *(uint4*)(dst + sw128(byte)) = v;
    }
}
__device__ __forceinline__ void issue_mma1(uint32_t sdst, uint64_t qdesc,
                                           uint64_t kdesc, uint32_t mbar) {
    #pragma unroll
    for (int s = 0; s < 16; ++s) {
        mma_f16_ss(sdst, qdesc + (uint64_t)((s >> 2) * 1024 + (s & 3) * 2),
                         kdesc + (uint64_t)((s >> 2) * 1024 + (s & 3) * 2),
                   IDESC1, (uint32_t)(s > 0));
    }
    TC_COMMIT(mbar);
}
#endif

__global__ __launch_bounds__(512, 1) void attn_tc_kernel(float* __restrict__ out)
{
#if TC_OK
    extern __shared__ char sm[];
    const uint32_t smb = smem_u32(sm);
    const int tid = threadIdx.x;
    const int wid = tid >> 5;
    const int sp  = wid & 3;
    const int wg  = wid >> 2;
    const int lid = tid & 31;
    const int q0  = blockIdx.x * 128;
    const int b   = blockIdx.y;

    if (wid == 0) {
        TC_ALLOC(smb + SM_PTR, 512);
        TC_RELINQ();
        if (elect_one()) { MBAR_INIT(smb + SM_M1, 1); MBAR_INIT(smb + SM_M2, 1); }
    }
    __syncthreads();
    uint32_t tmem;
    asm volatile("ld.shared.b32 %0, [%1];" : "=r"(tmem) : "r"(smb + SM_PTR));
    const uint32_t woff = (uint32_t)sp << 21;

    const uint64_t qdesc = make_desc(smb + SM_Q);
    const uint64_t kdesc = make_desc(smb + SM_K);
    const uint64_t vdesc = make_desc(smb + SM_V);

    load_qk_tile(sm + SM_Q, g_q + ((size_t)b * NTOK + q0) * EMB, tid);
    load_qk_tile(sm + SM_K, g_k + (size_t)b * NTOK * EMB, tid);
    FENCE_ASYNC_SHARED();
    __syncthreads();
    if (wid == 0) {
        TC_FENCE_AFTER();
        if (elect_one()) issue_mma1(tmem + TM_S, qdesc, kdesc, smb + SM_M1);
    }

    float lsum = 0.f;
    int ph1 = 0, ph2 = 0;

    for (int itn = 0; itn < NITER; ++itn) {
        const int k0 = itn * TCK;

        // (a) wait MMA1(n): S ready
        MBAR_WAIT(smb + SM_M1, ph1); ph1 ^= 1;
        TC_FENCE_AFTER();

        // (b) read S (32 fp32 cols per warpgroup) into regs; S region then free
        uint32_t sreg[32];
        LDTM_X32(sreg, tmem + TM_S + (uint32_t)(wg << 5) + woff);
        TC_WAIT_LD();
        __syncthreads();   // all wgs done reading S

        // (c) load K(n+1); issue MMA1(n+1) into the (now free) S buffer
        if (itn < NITER - 1) {
            load_qk_tile(sm + SM_K, g_k + ((size_t)b * NTOK + k0 + TCK) * EMB, tid);
            FENCE_ASYNC_SHARED();
            __syncthreads();
            if (wid == 0) {
                TC_FENCE_AFTER();
                if (elect_one())
                    issue_mma1(tmem + TM_S, qdesc, kdesc, smb + SM_M1);
            }
        }

        // (d) exp2 + pack fp32->f16x2 (overlaps MMA1(n+1) on the tensor pipe)
        uint32_t pr[16];
        {
            float part = 0.f;
            #pragma unroll
            for (int j = 0; j < 16; ++j) {
                const float p0 = exp2f(__uint_as_float(sreg[2 * j]));
                const float p1 = exp2f(__uint_as_float(sreg[2 * j + 1]));
                part += p0 + p1;
                asm("cvt.rn.f16x2.f32 %0, %1, %2;" : "=r"(pr[j]) : "f"(p1), "f"(p0));
            }
            lsum += part;
        }

        // (e) wait MMA2(n-1): P region + V buffer free
        if (itn > 0) { MBAR_WAIT(smb + SM_M2, ph2); ph2 ^= 1; }
        TC_FENCE_AFTER();

        // (f) load V(n) + store P(n); issue MMA2(n)
        {
            const __half* gvt = g_vt + (size_t)b * EMB * NTOK + k0;
            #pragma unroll 8
            for (int it = 0; it < 8; ++it) {
                const int idx = tid + it * 512;
                const int r = idx >> 4;
                const int c = idx & 15;
                uint4 v = *(const uint4*)&gvt[(size_t)r * NTOK + c * 8];
                uint32_t byte = (uint32_t)(((r >> 3) + (c >> 3) * 32) * 1024
                                           + (r & 7) * 128 + (c & 7) * 16);
                *(uint4*)(sm + SM_V + sw128(byte)) = v;
            }
            STTM_X16(tmem + TM_P + (uint32_t)(wg << 4) + woff, pr);
            TC_WAIT_ST();
        }
        TC_FENCE_BEFORE();
        FENCE_ASYNC_SHARED();
        __syncthreads();
        if (wid == 0) {
            TC_FENCE_AFTER();
            if (elect_one()) {
                #pragma unroll
                for (int s = 0; s < 8; ++s) {
                    mma_f16_ts(tmem + TM_O, tmem + TM_P + s * 8,
                               vdesc + (uint64_t)((s >> 2) * 2048 + (s & 3) * 2),
                               IDESC2, (uint32_t)((itn > 0) | (s > 0)));
                }
                TC_COMMIT(smb + SM_M2);
            }
        }
    }

    // epilogue
    MBAR_WAIT(smb + SM_M2, ph2); ph2 ^= 1;
    TC_FENCE_AFTER();
    {
        float* lpart = (float*)(sm + SM_L);
        const int row = sp * 32 + lid;
        lpart[wg * 128 + row] = lsum;
        __syncthreads();
        const float inv = 1.f / (lpart[row] + lpart[128 + row]
                               + lpart[256 + row] + lpart[384 + row]);

        float* ob = out + ((size_t)b * NTOK + q0 + row) * EMB + wg * 64;
        #pragma unroll
        for (int ch = 0; ch < 2; ++ch) {
            uint32_t r[32];
            LDTM_X32(r, tmem + TM_O + (uint32_t)(wg * 64 + ch * 32) + woff);
            TC_WAIT_LD();
            #pragma unroll
            for (int j = 0; j < 32; j += 4) {
                float4 o;
                o.x = __uint_as_float(r[j + 0]) * inv;
                o.y = __uint_as_float(r[j + 1]) * inv;
                o.z = __uint_as_float(r[j + 2]) * inv;
                o.w = __uint_as_float(r[j + 3]) * inv;
                *(float4*)&ob[ch * 32 + j] = o;
            }
        }
    }
    __syncthreads();
    if (wid == 0) {
        if (elect_one()) { MBAR_INVAL(smb + SM_M1); MBAR_INVAL(smb + SM_M2); }
        TC_DEALLOC(tmem, 512);
    }
#endif
}

// ---------------------------------------------------------------------------
extern "C" void kernel_launch(void* const* d_in, const int* in_sizes, int n_in,
                              void* d_out, int out_size)
{
    const float* x  = (const float*)d_in[0];
    const float* Wq = (const float*)d_in[1];
    const float* bq = (const float*)d_in[2];
    const float* Wk = (const float*)d_in[3];
    const float* bk = (const float*)d_in[4];
    const float* Wv = (const float*)d_in[5];
    const float* bv = (const float*)d_in[6];
    float* out = (float*)d_out;

    cudaFuncSetAttribute(proj_tc_kernel,
                         cudaFuncAttributeMaxDynamicSharedMemorySize, PROJ_SMEM);
    cudaFuncSetAttribute(attn_tc_kernel,
                         cudaFuncAttributeMaxDynamicSharedMemorySize, ATT_SMEM);

    dim3 gproj(NTOK / 128, BATCH);
    proj_tc_kernel<<<gproj, 256, PROJ_SMEM>>>(x, Wq, bq, Wk, bk, Wv, bv);

    dim3 gatt(NTOK / 128, BATCH);
    attn_tc_kernel<<<gatt, 512, ATT_SMEM>>>(out);
}

// round 12
// speedup vs baseline: 2.7571x; 1.0978x over previous
#include <cuda_runtime.h>
#include <cuda_fp16.h>
#include <cstdint>

#define BATCH 4
#define EMB   256
#define NTOK  4096
#define TCK   128
#define NITER (NTOK / TCK)
#define LOG2E 1.4426950408889634f

__device__ __half g_q [(size_t)BATCH * NTOK * EMB];
__device__ __half g_k [(size_t)BATCH * NTOK * EMB];
__device__ __half g_vt[(size_t)BATCH * EMB * NTOK];

#if defined(__CUDA_ARCH_FEAT_SM103_ALL) || defined(__CUDA_ARCH_FEAT_SM100_ALL) || \
    defined(__CUDA_ARCH_FEAT_SM101_ALL) || defined(__CUDA_ARCH_SPECIFIC__)
#define TC_OK 1
#else
#define TC_OK 0
#endif

#if TC_OK
__device__ __forceinline__ uint32_t smem_u32(const void* p) {
    uint32_t a;
    asm("{ .reg .u64 t; cvta.to.shared.u64 t, %1; cvt.u32.u64 %0, t; }"
        : "=r"(a) : "l"(p));
    return a;
}
__device__ __forceinline__ uint32_t elect_one() {
    uint32_t pred;
    asm volatile("{\n\t.reg .pred p;\n\telect.sync _|p, 0xFFFFFFFF;\n\t"
                 "selp.b32 %0, 1, 0, p;\n\t}" : "=r"(pred));
    return pred;
}
__device__ __forceinline__ float f2tf32(float f) {
    uint32_t u;
    asm("cvt.rna.tf32.f32 %0, %1;" : "=r"(u) : "f"(f));
    return __uint_as_float(u);
}

#define MBAR_INIT(mbar, cnt) \
    asm volatile("mbarrier.init.shared.b64 [%0], %1;" :: "r"(mbar), "r"(cnt) : "memory")
#define MBAR_INVAL(mbar) \
    asm volatile("mbarrier.inval.shared.b64 [%0];" :: "r"(mbar) : "memory")
#define MBAR_WAIT(mbar, parity) do {                                             \
    uint32_t _mb = (mbar); uint32_t _ph = (parity); uint32_t _done;              \
    asm volatile("{\n\t.reg .pred p;\n\t"                                        \
        "mbarrier.try_wait.parity.acquire.cta.shared::cta.b64 p, [%1], %2;\n\t"  \
        "selp.b32 %0, 1, 0, p;\n\t}"                                             \
        : "=r"(_done) : "r"(_mb), "r"(_ph) : "memory");                          \
    if (!_done) {                                                                \
        asm volatile("{\n\t.reg .pred P1;\n\t"                                   \
            "WL_%=:\n\t"                                                         \
            "mbarrier.try_wait.parity.acquire.cta.shared::cta.b64 P1, [%0], %1, 0x989680;\n\t" \
            "@P1 bra.uni WD_%=;\n\t"                                             \
            "bra.uni WL_%=;\n\t"                                                 \
            "WD_%=:\n\t}" :: "r"(_mb), "r"(_ph) : "memory");                     \
    }                                                                            \
} while (0)

#define TC_ALLOC(dst_smem, ncols) \
    asm volatile("tcgen05.alloc.cta_group::1.sync.aligned.shared::cta.b32 [%0], %1;" \
                 :: "r"(dst_smem), "r"(ncols) : "memory")
#define TC_RELINQ() \
    asm volatile("tcgen05.relinquish_alloc_permit.cta_group::1.sync.aligned;")
#define TC_DEALLOC(tmem, ncols) \
    asm volatile("tcgen05.dealloc.cta_group::1.sync.aligned.b32 %0, %1;" \
                 :: "r"(tmem), "r"(ncols))
#define TC_COMMIT(mbar) \
    asm volatile("tcgen05.commit.cta_group::1.mbarrier::arrive::one.shared::cluster.b64 [%0];" \
                 :: "r"(mbar) : "memory")
#define TC_WAIT_LD()  asm volatile("tcgen05.wait::ld.sync.aligned;"  ::: "memory")
#define TC_WAIT_ST()  asm volatile("tcgen05.wait::st.sync.aligned;"  ::: "memory")
#define TC_FENCE_BEFORE() asm volatile("tcgen05.fence::before_thread_sync;" ::: "memory")
#define TC_FENCE_AFTER()  asm volatile("tcgen05.fence::after_thread_sync;"  ::: "memory")
#define FENCE_ASYNC_SHARED() asm volatile("fence.proxy.async.shared::cta;" ::: "memory")

#define CP_ASYNC16(dst, src) \
    asm volatile("cp.async.ca.shared.global [%0], [%1], 16;" \
                 :: "r"(dst), "l"(src) : "memory")
#define CP_COMMIT() asm volatile("cp.async.commit_group;" ::: "memory")
#define CP_WAIT0()  asm volatile("cp.async.wait_group 0;" ::: "memory")

#define LDTM_X32(r, addr) \
    asm volatile("tcgen05.ld.sync.aligned.32x32b.x32.b32 " \
        "{%0, %1, %2, %3, %4, %5, %6, %7, %8, %9, %10, %11, %12, %13, %14, %15, " \
        " %16, %17, %18, %19, %20, %21, %22, %23, %24, %25, %26, %27, %28, %29, %30, %31}, [%32];" \
        : "=r"((r)[0]),  "=r"((r)[1]),  "=r"((r)[2]),  "=r"((r)[3]),  \
          "=r"((r)[4]),  "=r"((r)[5]),  "=r"((r)[6]),  "=r"((r)[7]),  \
          "=r"((r)[8]),  "=r"((r)[9]),  "=r"((r)[10]), "=r"((r)[11]), \
          "=r"((r)[12]), "=r"((r)[13]), "=r"((r)[14]), "=r"((r)[15]), \
          "=r"((r)[16]), "=r"((r)[17]), "=r"((r)[18]), "=r"((r)[19]), \
          "=r"((r)[20]), "=r"((r)[21]), "=r"((r)[22]), "=r"((r)[23]), \
          "=r"((r)[24]), "=r"((r)[25]), "=r"((r)[26]), "=r"((r)[27]), \
          "=r"((r)[28]), "=r"((r)[29]), "=r"((r)[30]), "=r"((r)[31]) \
        : "r"(addr))

#define STTM_X16(addr, r) \
    asm volatile("tcgen05.st.sync.aligned.32x32b.x16.b32 [%0], " \
        "{%1, %2, %3, %4, %5, %6, %7, %8, %9, %10, %11, %12, %13, %14, %15, %16};" \
        :: "r"(addr), \
           "r"((r)[0]),  "r"((r)[1]),  "r"((r)[2]),  "r"((r)[3]),  \
           "r"((r)[4]),  "r"((r)[5]),  "r"((r)[6]),  "r"((r)[7]),  \
           "r"((r)[8]),  "r"((r)[9]),  "r"((r)[10]), "r"((r)[11]), \
           "r"((r)[12]), "r"((r)[13]), "r"((r)[14]), "r"((r)[15]) \
        : "memory")

__device__ __forceinline__ uint64_t make_desc(uint32_t smem_addr) {
    return 0x4000404000010000ULL | ((uint64_t)(smem_addr >> 4) & 0x3FFF);
}
__device__ __forceinline__ void mma_tf32_ss(uint32_t d, uint64_t a, uint64_t b,
                                            uint32_t idesc, uint32_t en) {
    asm volatile("{\n\t.reg .pred p;\n\tsetp.ne.u32 p, %5, 0;\n\t"
        "tcgen05.mma.cta_group::1.kind::tf32 [%0], %1, %2, %3, {%4, %4, %4, %4}, p;\n\t}"
        :: "r"(d), "l"(a), "l"(b), "r"(idesc), "r"(0u), "r"(en) : "memory");
}
__device__ __forceinline__ void mma_f16_ss(uint32_t d, uint64_t a, uint64_t b,
                                           uint32_t idesc, uint32_t en) {
    asm volatile("{\n\t.reg .pred p;\n\tsetp.ne.u32 p, %5, 0;\n\t"
        "tcgen05.mma.cta_group::1.kind::f16 [%0], %1, %2, %3, {%4, %4, %4, %4}, p;\n\t}"
        :: "r"(d), "l"(a), "l"(b), "r"(idesc), "r"(0u), "r"(en) : "memory");
}
__device__ __forceinline__ void mma_f16_ts(uint32_t d, uint32_t a, uint64_t b,
                                           uint32_t idesc, uint32_t en) {
    asm volatile("{\n\t.reg .pred p;\n\tsetp.ne.u32 p, %5, 0;\n\t"
        "tcgen05.mma.cta_group::1.kind::f16 [%0], [%1], %2, %3, {%4, %4, %4, %4}, p;\n\t}"
        :: "r"(d), "r"(a), "l"(b), "r"(idesc), "r"(0u), "r"(en) : "memory");
}
__device__ __forceinline__ uint32_t sw128(uint32_t b) { return b ^ ((b >> 3) & 0x70); }
#endif  // TC_OK

// ============================================================================
// tcgen05 QKV projection (UNCHANGED from R11 pass; fp16 outputs).
// ============================================================================
#define PSM_X   0
#define PSM_W   131072
#define PSM_PTR 196608
#define PSM_MB  196616
#define PROJ_SMEM 196640
#define IDESC_P ((1u << 4) | (2u << 7) | (2u << 10) | (4u << 17) | (8u << 24))

__global__ __launch_bounds__(256, 1) void proj_tc_kernel(
    const float* __restrict__ x,
    const float* __restrict__ Wq, const float* __restrict__ bq,
    const float* __restrict__ Wk, const float* __restrict__ bk,
    const float* __restrict__ Wv, const float* __restrict__ bv)
{
#if TC_OK
    extern __shared__ char sm[];
    const uint32_t smb = smem_u32(sm);
    const int tid = threadIdx.x;
    const int wid = tid >> 5;
    const int sp  = wid & 3;
    const int wg  = wid >> 2;
    const int lid = tid & 31;
    const int n0  = blockIdx.x * 128;
    const int b   = blockIdx.y;

    if (wid == 0) {
        TC_ALLOC(smb + PSM_PTR, 512);
        TC_RELINQ();
        if (elect_one()) {
            MBAR_INIT(smb + PSM_MB + 0, 1);
            MBAR_INIT(smb + PSM_MB + 8, 1);
        }
    }
    __syncthreads();
    uint32_t tmem;
    asm volatile("ld.shared.b32 %0, [%1];" : "=r"(tmem) : "r"(smb + PSM_PTR));
    const uint32_t woff = (uint32_t)sp << 21;
    const int n = sp * 32 + lid;

    {
        const float* xb = x + (size_t)b * EMB * NTOK + n0;
        #pragma unroll 8
        for (int it = 0; it < 32; ++it) {
            const int idx = tid + it * 256;
            const int c   = idx >> 5;
            const int nc4 = idx & 31;
            float4 v = *(const float4*)&xb[(size_t)c * NTOK + nc4 * 4];
            const uint32_t cb = (uint32_t)((c >> 5) * 16384 + ((c >> 2) & 7) * 16 + (c & 3) * 4);
            #pragma unroll
            for (int k2 = 0; k2 < 4; ++k2) {
                const int nn = nc4 * 4 + k2;
                uint32_t byte = cb + (uint32_t)((nn >> 3) * 1024 + (nn & 7) * 128);
                *(float*)(sm + PSM_X + sw128(byte)) =
                    f2tf32(k2 == 0 ? v.x : k2 == 1 ? v.y : k2 == 2 ? v.z : v.w);
            }
        }
    }

    const uint64_t xdesc = make_desc(smb + PSM_X);
    const float* Ws[3] = { Wq, Wk, Wv };
    int php[2] = { 0, 0 };

    for (int i = 0; i < 24; ++i) {
        const int bi = i & 1;
        if (i >= 2) { MBAR_WAIT(smb + PSM_MB + bi * 8, php[bi]); php[bi] ^= 1; }

        if (i == 16) {
            TC_FENCE_AFTER();
            const float scl = 0.0625f * LOG2E;
            __half* dst0 = g_q + ((size_t)b * NTOK + n0 + n) * EMB;
            #pragma unroll
            for (int cc = 0; cc < 4; ++cc) {
                const int col0 = wg * 128 + cc * 32;
                uint32_t r[32];
                LDTM_X32(r, tmem + (uint32_t)col0 + woff);
                TC_WAIT_LD();
                #pragma unroll
                for (int j = 0; j < 32; j += 8) {
                    uint32_t w[4];
                    #pragma unroll
                    for (int k2 = 0; k2 < 4; ++k2) {
                        const float v0 = (__uint_as_float(r[j+2*k2+0]) + __ldg(&bq[col0+j+2*k2+0])) * scl;
                        const float v1 = (__uint_as_float(r[j+2*k2+1]) + __ldg(&bq[col0+j+2*k2+1])) * scl;
                        asm("cvt.rn.f16x2.f32 %0, %1, %2;" : "=r"(w[k2]) : "f"(v1), "f"(v0));
                    }
                    uint4 o; o.x = w[0]; o.y = w[1]; o.z = w[2]; o.w = w[3];
                    *(uint4*)&dst0[col0 + j] = o;
                }
            }
            TC_FENCE_BEFORE();
            __syncthreads();
        }

        {
            const float* W = Ws[i >> 3] + (size_t)((i & 7) * 32) * EMB;
            char* buf = sm + PSM_W + bi * 32768;
            #pragma unroll
            for (int it = 0; it < 8; ++it) {
                const int idx = tid + it * 256;
                const int r  = idx >> 6;
                const int c4 = idx & 63;
                float4 v = *(const float4*)&W[(size_t)r * EMB + c4 * 4];
                v.x = f2tf32(v.x); v.y = f2tf32(v.y);
                v.z = f2tf32(v.z); v.w = f2tf32(v.w);
                uint32_t byte = (uint32_t)(((r >> 3) + (c4 >> 3) * 4) * 1024
                                           + (r & 7) * 128 + (c4 & 7) * 16);
                *(float4*)(buf + sw128(byte)) = v;
            }
        }
        FENCE_ASYNC_SHARED();
        __syncthreads();

        if (wid == 0) {
            TC_FENCE_AFTER();
            if (elect_one()) {
                const uint64_t wd = make_desc(smb + PSM_W + (uint32_t)(bi * 32768));
                const uint32_t dtm = tmem + (uint32_t)(((i >> 3) == 1 ? 256 : 0) + (i & 7) * 32);
                #pragma unroll
                for (int s = 0; s < 32; ++s) {
                    mma_tf32_ss(dtm, xdesc + (uint64_t)((s >> 2) * 1024 + (s & 3) * 2),
                                     wd    + (uint64_t)((s >> 2) * 256  + (s & 3) * 2),
                                IDESC_P, (uint32_t)(s > 0));
                }
                TC_COMMIT(smb + PSM_MB + bi * 8);
            }
        }
    }
    MBAR_WAIT(smb + PSM_MB + 0, php[0]); php[0] ^= 1;
    MBAR_WAIT(smb + PSM_MB + 8, php[1]); php[1] ^= 1;
    TC_FENCE_AFTER();

    {
        __half* dst = g_k + ((size_t)b * NTOK + n0 + n) * EMB;
        #pragma unroll
        for (int cc = 0; cc < 4; ++cc) {
            const int col0 = wg * 128 + cc * 32;
            uint32_t r[32];
            LDTM_X32(r, tmem + (uint32_t)(256 + col0) + woff);
            TC_WAIT_LD();
            #pragma unroll
            for (int j = 0; j < 32; j += 8) {
                uint32_t w[4];
                #pragma unroll
                for (int k2 = 0; k2 < 4; ++k2) {
                    const float v0 = __uint_as_float(r[j+2*k2+0]) + __ldg(&bk[col0+j+2*k2+0]);
                    const float v1 = __uint_as_float(r[j+2*k2+1]) + __ldg(&bk[col0+j+2*k2+1]);
                    asm("cvt.rn.f16x2.f32 %0, %1, %2;" : "=r"(w[k2]) : "f"(v1), "f"(v0));
                }
                uint4 o; o.x = w[0]; o.y = w[1]; o.z = w[2]; o.w = w[3];
                *(uint4*)&dst[col0 + j] = o;
            }
        }
    }
    {
        __half* vt = g_vt + (size_t)b * EMB * NTOK + n0 + n;
        #pragma unroll
        for (int cc = 0; cc < 4; ++cc) {
            const int col0 = wg * 128 + cc * 32;
            uint32_t r[32];
            LDTM_X32(r, tmem + (uint32_t)col0 + woff);
            TC_WAIT_LD();
            #pragma unroll
            for (int j = 0; j < 32; ++j) {
                const float v = __uint_as_float(r[j]) + __ldg(&bv[col0 + j]);
                vt[(size_t)(col0 + j) * NTOK] = __float2half(v);
            }
        }
    }
    __syncthreads();
    if (wid == 0) {
        if (elect_one()) { MBAR_INVAL(smb + PSM_MB + 0); MBAR_INVAL(smb + PSM_MB + 8); }
        TC_DEALLOC(tmem, 512);
    }
#endif
}

// ============================================================================
// fp16 tcgen05 attention v3: cp.async prefetch + tensor-pipe-saturating order.
// CTA = (128 q, batch), 512 threads. SMEM: Q 64KB + K 64KB + V 64KB.
// TMEM: S@0 (128 fp32), P@128 (64 f16x2), O@256 (256 fp32).
// Iter: wait mb1(n) -> cp.async K(n+1) -> LDTM S -> cp.wait -> sync ->
//       issue MMA1(n+1) -> wait mb2(n-1) -> cp.async V(n) -> exp(f16x2) ->
//       STTM P -> cp.wait -> sync -> issue MMA2(n).
// ============================================================================
#define SM_Q   0
#define SM_K   65536
#define SM_V   131072
#define SM_PTR 196608
#define SM_M1  196616
#define SM_M2  196624
#define SM_L   196640
#define ATT_SMEM (196640 + 4 * 128 * 4)
#define TM_S 0
#define TM_P 128
#define TM_O 256
#define IDESC1 ((1u << 4) | (16u << 17) | (8u << 24))
#define IDESC2 ((1u << 4) | (32u << 17) | (8u << 24))

#if TC_OK
__device__ __forceinline__ void load_qk_tile(char* dst, const __half* g, int tid) {
    #pragma unroll 8
    for (int it = 0; it < 8; ++it) {
        const int idx = tid + it * 512;
        const int r = idx >> 5;
        const int c = idx & 31;
        uint4 v = *(const uint4*)&g[(size_t)r * EMB + c * 8];
        uint32_t byte = (uint32_t)(((r >> 3) + (c >> 3) * 16) * 1024
                                   + (r & 7) * 128 + (c & 7) * 16);
        *(uint4*)(dst + sw128(byte)) = v;
    }
}
__device__ __forceinline__ void cp_k_tile(uint32_t dst, const __half* g, int tid) {
    #pragma unroll
    for (int it = 0; it < 8; ++it) {
        const int idx = tid + it * 512;
        const int r = idx >> 5;
        const int c = idx & 31;
        uint32_t byte = (uint32_t)(((r >> 3) + (c >> 3) * 16) * 1024
                                   + (r & 7) * 128 + (c & 7) * 16);
        CP_ASYNC16(dst + sw128(byte), (const char*)(g + (size_t)r * EMB + c * 8));
    }
}
__device__ __forceinline__ void cp_v_tile(uint32_t dst, const __half* g, int tid) {
    #pragma unroll
    for (int it = 0; it < 8; ++it) {
        const int idx = tid + it * 512;
        const int r = idx >> 4;
        const int c = idx & 15;
        uint32_t byte = (uint32_t)(((r >> 3) + (c >> 3) * 32) * 1024
                                   + (r & 7) * 128 + (c & 7) * 16);
        CP_ASYNC16(dst + sw128(byte), (const char*)(g + (size_t)r * NTOK + c * 8));
    }
}
__device__ __forceinline__ void issue_mma1(uint32_t sdst, uint64_t qdesc,
                                           uint64_t kdesc, uint32_t mbar) {
    #pragma unroll
    for (int s = 0; s < 16; ++s) {
        mma_f16_ss(sdst, qdesc + (uint64_t)((s >> 2) * 1024 + (s & 3) * 2),
                         kdesc + (uint64_t)((s >> 2) * 1024 + (s & 3) * 2),
                   IDESC1, (uint32_t)(s > 0));
    }
    TC_COMMIT(mbar);
}
#endif

__global__ __launch_bounds__(512, 1) void attn_tc_kernel(float* __restrict__ out)
{
#if TC_OK
    extern __shared__ char sm[];
    const uint32_t smb = smem_u32(sm);
    const int tid = threadIdx.x;
    const int wid = tid >> 5;
    const int sp  = wid & 3;
    const int wg  = wid >> 2;
    const int lid = tid & 31;
    const int q0  = blockIdx.x * 128;
    const int b   = blockIdx.y;

    if (wid == 0) {
        TC_ALLOC(smb + SM_PTR, 512);
        TC_RELINQ();
        if (elect_one()) { MBAR_INIT(smb + SM_M1, 1); MBAR_INIT(smb + SM_M2, 1); }
    }
    __syncthreads();
    uint32_t tmem;
    asm volatile("ld.shared.b32 %0, [%1];" : "=r"(tmem) : "r"(smb + SM_PTR));
    const uint32_t woff = (uint32_t)sp << 21;

    const uint64_t qdesc = make_desc(smb + SM_Q);
    const uint64_t kdesc = make_desc(smb + SM_K);
    const uint64_t vdesc = make_desc(smb + SM_V);

    const __half* gk = g_k + (size_t)b * NTOK * EMB;
    const __half* gv = g_vt + (size_t)b * EMB * NTOK;

    load_qk_tile(sm + SM_Q, g_q + ((size_t)b * NTOK + q0) * EMB, tid);
    load_qk_tile(sm + SM_K, gk, tid);
    FENCE_ASYNC_SHARED();
    __syncthreads();
    if (wid == 0) {
        TC_FENCE_AFTER();
        if (elect_one()) issue_mma1(tmem + TM_S, qdesc, kdesc, smb + SM_M1);
    }

    float lsum = 0.f;
    int ph1 = 0, ph2 = 0;

    for (int itn = 0; itn < NITER; ++itn) {
        const int k0 = itn * TCK;

        // (1) wait MMA1(n): S ready, K buffer free
        MBAR_WAIT(smb + SM_M1, ph1); ph1 ^= 1;
        TC_FENCE_AFTER();

        // (2) prefetch K(n+1) via cp.async (no registers)
        if (itn < NITER - 1) cp_k_tile(smb + SM_K, gk + (size_t)(k0 + TCK) * EMB, tid);
        CP_COMMIT();

        // (3) read S (frees S region for MMA1(n+1))
        uint32_t sreg[32];
        LDTM_X32(sreg, tmem + TM_S + (uint32_t)(wg << 5) + woff);
        TC_WAIT_LD();

        // (4) K(n+1) landed + all warps read S -> issue MMA1(n+1)
        CP_WAIT0();
        FENCE_ASYNC_SHARED();
        __syncthreads();
        if (itn < NITER - 1 && wid == 0) {
            TC_FENCE_AFTER();
            if (elect_one()) issue_mma1(tmem + TM_S, qdesc, kdesc, smb + SM_M1);
        }

        // (5) wait MMA2(n-1): P region + V buffer free; prefetch V(n)
        if (itn > 0) { MBAR_WAIT(smb + SM_M2, ph2); ph2 ^= 1; }
        TC_FENCE_AFTER();
        cp_v_tile(smb + SM_V, gv + k0, tid);
        CP_COMMIT();

        // (6) softmax in f16x2: P = ex2(S), lsum from the exact stored P values
        uint32_t pr[16];
        {
            float part = 0.f;
            #pragma unroll
            for (int j = 0; j < 16; ++j) {
                uint32_t h2;
                asm("cvt.rn.f16x2.f32 %0, %1, %2;" : "=r"(h2)
                    : "f"(__uint_as_float(sreg[2 * j + 1])),
                      "f"(__uint_as_float(sreg[2 * j])));
                asm("ex2.approx.f16x2 %0, %1;" : "=r"(pr[j]) : "r"(h2));
                const float2 f = __half22float2(*(__half2*)&pr[j]);
                part += f.x + f.y;
            }
            lsum += part;
        }

        // (7) store P; V landed; issue MMA2(n)
        STTM_X16(tmem + TM_P + (uint32_t)(wg << 4) + woff, pr);
        TC_WAIT_ST();
        TC_FENCE_BEFORE();
        CP_WAIT0();
        FENCE_ASYNC_SHARED();
        __syncthreads();
        if (wid == 0) {
            TC_FENCE_AFTER();
            if (elect_one()) {
                #pragma unroll
                for (int s = 0; s < 8; ++s) {
                    mma_f16_ts(tmem + TM_O, tmem + TM_P + s * 8,
                               vdesc + (uint64_t)((s >> 2) * 2048 + (s & 3) * 2),
                               IDESC2, (uint32_t)((itn > 0) | (s > 0)));
                }
                TC_COMMIT(smb + SM_M2);
            }
        }
    }

    // epilogue
    MBAR_WAIT(smb + SM_M2, ph2); ph2 ^= 1;
    TC_FENCE_AFTER();
    {
        float* lpart = (float*)(sm + SM_L);
        const int row = sp * 32 + lid;
        lpart[wg * 128 + row] = lsum;
        __syncthreads();
        const float inv = 1.f / (lpart[row] + lpart[128 + row]
                               + lpart[256 + row] + lpart[384 + row]);

        float* ob = out + ((size_t)b * NTOK + q0 + row) * EMB + wg * 64;
        #pragma unroll
        for (int ch = 0; ch < 2; ++ch) {
            uint32_t r[32];
            LDTM_X32(r, tmem + TM_O + (uint32_t)(wg * 64 + ch * 32) + woff);
            TC_WAIT_LD();
            #pragma unroll
            for (int j = 0; j < 32; j += 4) {
                float4 o;
                o.x = __uint_as_float(r[j + 0]) * inv;
                o.y = __uint_as_float(r[j + 1]) * inv;
                o.z = __uint_as_float(r[j + 2]) * inv;
                o.w = __uint_as_float(r[j + 3]) * inv;
                *(float4*)&ob[ch * 32 + j] = o;
            }
        }
    }
    __syncthreads();
    if (wid == 0) {
        if (elect_one()) { MBAR_INVAL(smb + SM_M1); MBAR_INVAL(smb + SM_M2); }
        TC_DEALLOC(tmem, 512);
    }
#endif
}

// ---------------------------------------------------------------------------
extern "C" void kernel_launch(void* const* d_in, const int* in_sizes, int n_in,
                              void* d_out, int out_size)
{
    const float* x  = (const float*)d_in[0];
    const float* Wq = (const float*)d_in[1];
    const float* bq = (const float*)d_in[2];
    const float* Wk = (const float*)d_in[3];
    const float* bk = (const float*)d_in[4];
    const float* Wv = (const float*)d_in[5];
    const float* bv = (const float*)d_in[6];
    float* out = (float*)d_out;

    cudaFuncSetAttribute(proj_tc_kernel,
                         cudaFuncAttributeMaxDynamicSharedMemorySize, PROJ_SMEM);
    cudaFuncSetAttribute(attn_tc_kernel,
                         cudaFuncAttributeMaxDynamicSharedMemorySize, ATT_SMEM);

    dim3 gproj(NTOK / 128, BATCH);
    proj_tc_kernel<<<gproj, 256, PROJ_SMEM>>>(x, Wq, bq, Wk, bk, Wv, bv);

    dim3 gatt(NTOK / 128, BATCH);
    attn_tc_kernel<<<gatt, 512, ATT_SMEM>>>(out);
}